// round 6
// baseline (speedup 1.0000x reference)
#include <cuda_runtime.h>
#include <cuda_bf16.h>
#include <math.h>
#include <stdint.h>

#define B_ 4
#define L_ 4096
#define D_ 2048
#define M_ (B_*L_)            // 16384 rows
#define LCHUNK 128
#define NCHUNK (L_/LCHUNK)    // 32

// GEMM tiling: CTA tile 128(M) x 256(N), K chunk 32 bf16 (=64B row, SW64)
// 8 warps, warp tile 64x64.
#define KC 32
#define NKCH (D_/KC)          // 64
#define A_SUB 8192            // 128 rows * 64B
#define B_SUB 16384           // 256 rows * 64B
#define STAGE (2*A_SUB + 2*B_SUB)   // Ah, Al, Bh, Bl = 48KB
#define SMEM_TOTAL (2*STAGE)        // 96KB double buffered

// ---------------- scratch (device globals; no allocation allowed) ----------
__device__ float g_gate[33554432];   // [M_, D_] sigmoid(f)
__device__ float g_bin [33554432];   // [M_, D_] silu(i); becomes o after scan
__device__ float g_g   [33554432];   // [M_, D_] g projection (raw)
__device__ float g_cA  [B_*NCHUNK*D_];
__device__ float g_cH  [B_*NCHUNK*D_];
__device__ float g_pre [B_*NCHUNK*D_];
__device__ __nv_bfloat16 g_Xhi[33554432], g_Xlo[33554432];
__device__ __nv_bfloat16 g_Whi[4][4194304], g_Wlo[4][4194304]; // Wi,Wf,Wg,Wo
__device__ __nv_bfloat16 g_oHi[33554432], g_oLo[33554432];     // rms-gated out

__device__ __forceinline__ float fsigmoid(float x) {
    return 1.0f / (1.0f + __expf(-x));
}

// ---------------------------- PTX helpers ----------------------------------
__device__ __forceinline__ uint32_t smem_u32(const void* p) {
    uint32_t a;
    asm("{ .reg .u64 t; cvta.to.shared.u64 t, %1; cvt.u32.u64 %0, t; }"
        : "=r"(a) : "l"(p));
    return a;
}
__device__ __forceinline__ uint32_t swz64(uint32_t off) {
    return off ^ ((off >> 3) & 0x30);
}
__device__ __forceinline__ void cpa16(uint32_t s, const void* g) {
    asm volatile("cp.async.cg.shared.global [%0], [%1], 16;" :: "r"(s), "l"(g));
}
#define CPA_COMMIT()  asm volatile("cp.async.commit_group;" ::: "memory")
#define CPA_WAIT1()   asm volatile("cp.async.wait_group 1;" ::: "memory")
#define CPA_WAIT0()   asm volatile("cp.async.wait_group 0;" ::: "memory")

__device__ __forceinline__ void ldsm4(uint32_t* r, uint32_t addr) {
    asm volatile("ldmatrix.sync.aligned.m8n8.x4.shared.b16 {%0,%1,%2,%3}, [%4];"
        : "=r"(r[0]), "=r"(r[1]), "=r"(r[2]), "=r"(r[3]) : "r"(addr));
}
__device__ __forceinline__ void mma_bf16(float* c, const uint32_t* a,
                                         uint32_t b0, uint32_t b1) {
    asm volatile(
        "mma.sync.aligned.m16n8k16.row.col.f32.bf16.bf16.f32 "
        "{%0,%1,%2,%3}, {%4,%5,%6,%7}, {%8,%9}, {%0,%1,%2,%3};"
        : "+f"(c[0]), "+f"(c[1]), "+f"(c[2]), "+f"(c[3])
        : "r"(a[0]), "r"(a[1]), "r"(a[2]), "r"(a[3]), "r"(b0), "r"(b1));
}

// ---------------------------------------------------------------------------
// fp32 -> bf16 hi/lo splits (vectorized: float4 in, 4xbf16 = 8B out per array)
// ---------------------------------------------------------------------------
__device__ __forceinline__ void split4(const float4 v, uint2* hi4, uint2* lo4) {
    __nv_bfloat16 h[4], l[4];
    float f[4] = {v.x, v.y, v.z, v.w};
    #pragma unroll
    for (int q = 0; q < 4; q++) {
        h[q] = __float2bfloat16(f[q]);
        l[q] = __float2bfloat16(f[q] - __bfloat162float(h[q]));
    }
    *hi4 = *reinterpret_cast<uint2*>(h);
    *lo4 = *reinterpret_cast<uint2*>(l);
}

__global__ __launch_bounds__(256) void splitX_kernel(const float* __restrict__ src) {
    int i = blockIdx.x * 256 + threadIdx.x;          // float4 index
    float4 v = reinterpret_cast<const float4*>(src)[i];
    uint2 h, l;
    split4(v, &h, &l);
    reinterpret_cast<uint2*>(g_Xhi)[i] = h;
    reinterpret_cast<uint2*>(g_Xlo)[i] = l;
}

__global__ __launch_bounds__(256) void splitW_kernel(
    const float* __restrict__ w0, const float* __restrict__ w1,
    const float* __restrict__ w2, const float* __restrict__ w3) {
    const float* src = (blockIdx.y == 0) ? w0 : (blockIdx.y == 1) ? w1
                     : (blockIdx.y == 2) ? w2 : w3;
    int i = blockIdx.x * 256 + threadIdx.x;          // float4 index
    float4 v = reinterpret_cast<const float4*>(src)[i];
    uint2 h, l;
    split4(v, &h, &l);
    reinterpret_cast<uint2*>(g_Whi[blockIdx.y])[i] = h;
    reinterpret_cast<uint2*>(g_Wlo[blockIdx.y])[i] = l;
}

// ---------------------------------------------------------------------------
// Split-bf16 HMMA GEMM: C[m,n] = sum_k A[m,k]*B[n,k]
// 3 MMAs per product: Ah*Bh + Ah*Bl + Al*Bh, issued in independent waves of 8.
// CTA tile 128x256, K chunk 32, 8 warps (warp tile 64x64).
// fused=1: projection (blockIdx.y = weight 0..2 -> silu/sigmoid/raw)
// fused=0: output GEMM (Wo, raw) into Cext.
// ---------------------------------------------------------------------------
__global__ __launch_bounds__(256, 1) void gemm_split(int fused, float* Cext) {
    extern __shared__ char smem[];
    const uint32_t sb = smem_u32(smem);
    const int tid  = threadIdx.x;
    const int lane = tid & 31;
    const int wid  = tid >> 5;
    const int wm   = wid & 1;      // 2 warps over M (64 rows each)
    const int wn   = wid >> 1;     // 4 warps over N (64 cols each)
    const int bn = blockIdx.x;
    const int w  = fused ? blockIdx.y : 3;
    const int bm = blockIdx.z;
    const int mode = fused ? ((w == 0) ? 0 : (w == 1) ? 1 : 2) : 2;

    const __nv_bfloat16* Ah = fused ? g_Xhi : g_oHi;
    const __nv_bfloat16* Al = fused ? g_Xlo : g_oLo;
    const __nv_bfloat16* Bh = g_Whi[w];
    const __nv_bfloat16* Bl = g_Wlo[w];
    float* C = fused ? ((w == 0) ? g_bin : (w == 1) ? g_gate : g_g) : Cext;

    const size_t rowA = (size_t)bm * 128;
    const size_t rowB = (size_t)bn * 256;

    // acc[mt][g]: mt = m16 tile (4), g = n8 group (8) -> 128 floats
    float acc[4][8][4];
    #pragma unroll
    for (int mt = 0; mt < 4; mt++)
        #pragma unroll
        for (int g = 0; g < 8; g++)
            #pragma unroll
            for (int q = 0; q < 4; q++) acc[mt][g][q] = 0.0f;

    // prefetch one K chunk (32 bf16 = 64B/row) into stage (c&1)
    // slots: [0,512) Ah, [512,1024) Al, [1024,2048) Bh, [2048,3072) Bl
    auto prefetch = [&](int c) {
        const int k0 = c * KC;
        const uint32_t st = sb + (uint32_t)(c & 1) * STAGE;
        #pragma unroll
        for (int i = 0; i < 12; i++) {
            int slot = tid + i * 256;
            if (slot < 1024) {
                int arr = slot >> 9;            // 0=Ah, 1=Al
                int s   = slot & 511;
                int row = s >> 2, ch = s & 3;
                uint32_t so = swz64((uint32_t)row * 64 + ch * 16);
                size_t gA = (rowA + row) * D_ + k0 + ch * 8;
                cpa16(st + arr * A_SUB + so, (arr ? Al : Ah) + gA);
            } else {
                int s2  = slot - 1024;
                int arr = s2 >> 10;             // 0=Bh, 1=Bl
                int s   = s2 & 1023;
                int row = s >> 2, ch = s & 3;
                uint32_t so = swz64((uint32_t)row * 64 + ch * 16);
                size_t gB = (rowB + row) * D_ + k0 + ch * 8;
                cpa16(st + 2 * A_SUB + arr * B_SUB + so, (arr ? Bl : Bh) + gB);
            }
        }
        CPA_COMMIT();
    };

    prefetch(0);
    prefetch(1);

    const int rowL = lane & 15;     // ldmatrix row within 16
    const int colL = lane >> 4;     // 16B chunk selector

    for (int c = 0; c < NKCH; c++) {
        if (c < NKCH - 1) { CPA_WAIT1(); } else { CPA_WAIT0(); }
        __syncthreads();

        const uint32_t st = sb + (uint32_t)(c & 1) * STAGE;
        #pragma unroll
        for (int ks = 0; ks < 2; ks++) {
            uint32_t ah[4][4], al[4][4];
            #pragma unroll
            for (int mt = 0; mt < 4; mt++) {
                uint32_t off = swz64((uint32_t)(wm * 64 + mt * 16 + rowL) * 64
                                     + ks * 32 + colL * 16);
                ldsm4(ah[mt], st + 0 * A_SUB + off);
                ldsm4(al[mt], st + 1 * A_SUB + off);
            }
            #pragma unroll
            for (int g16 = 0; g16 < 4; g16++) {
                uint32_t boff = swz64((uint32_t)(wn * 64 + g16 * 16 + rowL) * 64
                                      + ks * 32 + colL * 16);
                uint32_t bh[4], bl[4];
                ldsm4(bh, st + 2 * A_SUB + boff);
                ldsm4(bl, st + 2 * A_SUB + B_SUB + boff);
                // wave 1: hh (8 independent accs)
                #pragma unroll
                for (int mt = 0; mt < 4; mt++)
                    #pragma unroll
                    for (int na = 0; na < 2; na++)
                        mma_bf16(acc[mt][g16 * 2 + na], ah[mt], bh[na], bh[na + 2]);
                // wave 2: hl
                #pragma unroll
                for (int mt = 0; mt < 4; mt++)
                    #pragma unroll
                    for (int na = 0; na < 2; na++)
                        mma_bf16(acc[mt][g16 * 2 + na], ah[mt], bl[na], bl[na + 2]);
                // wave 3: lh
                #pragma unroll
                for (int mt = 0; mt < 4; mt++)
                    #pragma unroll
                    for (int na = 0; na < 2; na++)
                        mma_bf16(acc[mt][g16 * 2 + na], al[mt], bh[na], bh[na + 2]);
            }
        }
        __syncthreads();
        if (c + 2 < NKCH) prefetch(c + 2);
    }

    // epilogue: direct float2 stores with fused activation
    #pragma unroll
    for (int mt = 0; mt < 4; mt++) {
        #pragma unroll
        for (int g = 0; g < 8; g++) {
            int n = (int)rowB + wn * 64 + (g >> 1) * 16 + (g & 1) * 8 + (lane & 3) * 2;
            size_t m0 = rowA + wm * 64 + mt * 16 + (lane >> 2);
            #pragma unroll
            for (int h = 0; h < 2; h++) {           // h=0: rows, h=1: rows+8
                float v0 = acc[mt][g][h * 2 + 0];
                float v1 = acc[mt][g][h * 2 + 1];
                if (mode == 0)      { v0 = v0 * fsigmoid(v0); v1 = v1 * fsigmoid(v1); }
                else if (mode == 1) { v0 = fsigmoid(v0);      v1 = fsigmoid(v1); }
                float2 pr = make_float2(v0, v1);
                *reinterpret_cast<float2*>(&C[(m0 + h * 8) * D_ + n]) = pr;
            }
        }
    }
}

// ---------------------------------------------------------------------------
// Chunked linear-recurrence scan: h_t = a_t*h_{t-1} + b_t,  b_t = si*(1-a_t)
// ---------------------------------------------------------------------------
__global__ void scan_pass1_kernel() {
    int d = blockIdx.x * 256 + threadIdx.x;
    int c = blockIdx.y;
    int b = blockIdx.z;
    size_t base = ((size_t)b * L_ + (size_t)c * LCHUNK) * D_ + d;
    float a = 1.0f, h = 0.0f;
    #pragma unroll 4
    for (int t = 0; t < LCHUNK; t++) {
        float gt = g_gate[base + (size_t)t * D_];
        float si = g_bin [base + (size_t)t * D_];
        h = fmaf(gt, h, si * (1.0f - gt));
        a *= gt;
    }
    size_t idx = ((size_t)b * NCHUNK + c) * D_ + d;
    g_cA[idx] = a;
    g_cH[idx] = h;
}

__global__ void scan_pass2_kernel() {
    int d = blockIdx.x * 256 + threadIdx.x;
    int b = blockIdx.y;
    float h = 0.0f;
    #pragma unroll
    for (int c = 0; c < NCHUNK; c++) {
        size_t idx = ((size_t)b * NCHUNK + c) * D_ + d;
        g_pre[idx] = h;
        h = fmaf(g_cA[idx], h, g_cH[idx]);
    }
}

__global__ void scan_pass3_kernel() {
    int d = blockIdx.x * 256 + threadIdx.x;
    int c = blockIdx.y;
    int b = blockIdx.z;
    size_t base = ((size_t)b * L_ + (size_t)c * LCHUNK) * D_ + d;
    float h = g_pre[((size_t)b * NCHUNK + c) * D_ + d];
    #pragma unroll 4
    for (int t = 0; t < LCHUNK; t++) {
        size_t p = base + (size_t)t * D_;
        float gt = g_gate[p];
        float si = g_bin [p];
        h = fmaf(gt, h, si * (1.0f - gt));
        g_bin[p] = h;           // o overwrites silu(i) in place
    }
}

// ---------------------------------------------------------------------------
// RMSNorm(g)*weight*swish(o); writes bf16 hi/lo split for the output GEMM.
// ---------------------------------------------------------------------------
__global__ __launch_bounds__(256) void rms_gate_kernel(const float* __restrict__ gw) {
    const int m = blockIdx.x;
    const int tid = threadIdx.x;
    const float4* grow = reinterpret_cast<const float4*>(g_g  + (size_t)m * D_);
    const float4* orow = reinterpret_cast<const float4*>(g_bin + (size_t)m * D_);
    const float4* wrow = reinterpret_cast<const float4*>(gw);

    float4 gv[2];
    float ss = 0.0f;
    #pragma unroll
    for (int s = 0; s < 2; s++) {
        gv[s] = grow[tid + s * 256];
        ss += gv[s].x * gv[s].x + gv[s].y * gv[s].y
            + gv[s].z * gv[s].z + gv[s].w * gv[s].w;
    }

    __shared__ float sh[8];
    __shared__ float tot;
    int lane = tid & 31, wid = tid >> 5;
    #pragma unroll
    for (int o = 16; o > 0; o >>= 1) ss += __shfl_xor_sync(0xffffffffu, ss, o);
    if (lane == 0) sh[wid] = ss;
    __syncthreads();
    if (wid == 0) {
        float v = (lane < 8) ? sh[lane] : 0.0f;
        #pragma unroll
        for (int o = 4; o > 0; o >>= 1) v += __shfl_xor_sync(0xffffffffu, v, o);
        if (lane == 0) tot = v;
    }
    __syncthreads();

    float rms = rsqrtf(tot * (1.0f / D_) + 1e-5f);

    #pragma unroll
    for (int s = 0; s < 2; s++) {
        float4 o4 = orow[tid + s * 256];
        float4 w4 = wrow[tid + s * 256];
        float4 r;
        r.x = gv[s].x * rms * w4.x * (o4.x * fsigmoid(o4.x));
        r.y = gv[s].y * rms * w4.y * (o4.y * fsigmoid(o4.y));
        r.z = gv[s].z * rms * w4.z * (o4.z * fsigmoid(o4.z));
        r.w = gv[s].w * rms * w4.w * (o4.w * fsigmoid(o4.w));
        uint2 h, l;
        split4(r, &h, &l);
        size_t b4 = (size_t)m * (D_ / 4) + tid + s * 256;
        reinterpret_cast<uint2*>(g_oHi)[b4] = h;
        reinterpret_cast<uint2*>(g_oLo)[b4] = l;
    }
}

// ---------------------------------------------------------------------------
extern "C" void kernel_launch(void* const* d_in, const int* in_sizes, int n_in,
                              void* d_out, int out_size)
{
    const float* X  = (const float*)d_in[0];
    const float* Wi = (const float*)d_in[1];
    const float* Wf = (const float*)d_in[2];
    const float* Wg = (const float*)d_in[3];
    const float* gw = (const float*)d_in[4];
    const float* Wo = (const float*)d_in[5];
    float* Y = (float*)d_out;

    static int smem_set = 0;
    if (!smem_set) {
        cudaFuncSetAttribute(gemm_split, cudaFuncAttributeMaxDynamicSharedMemorySize,
                             SMEM_TOTAL);
        smem_set = 1;
    }

    // fp32 -> bf16 hi/lo splits (vectorized)
    splitX_kernel<<<(M_ * D_ / 4) / 256, 256>>>(X);
    splitW_kernel<<<dim3((D_ * D_ / 4) / 256, 4), 256>>>(Wi, Wf, Wg, Wo);

    // fused i/f/g projections: grid y = weight, z = M tile (L2 A-tile reuse)
    gemm_split<<<dim3(D_ / 256, 3, M_ / 128), 256, SMEM_TOTAL>>>(1, Y);

    scan_pass1_kernel<<<dim3(D_ / 256, NCHUNK, B_), 256>>>();
    scan_pass2_kernel<<<dim3(D_ / 256, B_), 256>>>();
    scan_pass3_kernel<<<dim3(D_ / 256, NCHUNK, B_), 256>>>();

    rms_gate_kernel<<<M_, 256>>>(gw);

    // out @ Wo^T -> Y
    gemm_split<<<dim3(D_ / 256, 1, M_ / 128), 256, SMEM_TOTAL>>>(0, Y);
}

// round 7
// speedup vs baseline: 1.6061x; 1.6061x over previous
#include <cuda_runtime.h>
#include <cuda_fp16.h>
#include <math.h>
#include <stdint.h>

#define B_ 4
#define L_ 4096
#define D_ 2048
#define M_ (B_*L_)            // 16384 rows
#define LCHUNK 128
#define NCHUNK (L_/LCHUNK)    // 32

// GEMM tiling: 128x128 tile, K chunk 32 fp16 (=64B row, SW64 swizzle)
#define KC 32
#define NKCH (D_/KC)          // 64
#define SUB 8192              // 128 rows * 64B
#define STAGE (3*SUB)         // Ah, Al, B = 24KB
#define SMEM_TOTAL (2*STAGE)  // 48KB double buffered -> 2 CTAs/SM

// ---------------- scratch (device globals; no allocation allowed) ----------
__device__ float g_gate[33554432];   // [M_, D_] sigmoid(f)
__device__ float g_bin [33554432];   // [M_, D_] silu(i); becomes o after scan
__device__ float g_g   [33554432];   // [M_, D_] g projection (raw)
__device__ float g_cA  [B_*NCHUNK*D_];
__device__ float g_cH  [B_*NCHUNK*D_];
__device__ float g_pre [B_*NCHUNK*D_];
__device__ __half g_Xhi[33554432], g_Xlo[33554432];
__device__ __half g_Wh[4][4194304];               // Wi,Wf,Wg,Wo (fp16 rounded)
__device__ __half g_oHi[33554432], g_oLo[33554432]; // rms-gated out (hi/lo)

__device__ __forceinline__ float fsigmoid(float x) {
    return 1.0f / (1.0f + __expf(-x));
}

// ---------------------------- PTX helpers ----------------------------------
__device__ __forceinline__ uint32_t smem_u32(const void* p) {
    uint32_t a;
    asm("{ .reg .u64 t; cvta.to.shared.u64 t, %1; cvt.u32.u64 %0, t; }"
        : "=r"(a) : "l"(p));
    return a;
}
__device__ __forceinline__ uint32_t swz64(uint32_t off) {
    return off ^ ((off >> 3) & 0x30);
}
__device__ __forceinline__ void cpa16(uint32_t s, const void* g) {
    asm volatile("cp.async.cg.shared.global [%0], [%1], 16;" :: "r"(s), "l"(g));
}
#define CPA_COMMIT()  asm volatile("cp.async.commit_group;" ::: "memory")
#define CPA_WAIT1()   asm volatile("cp.async.wait_group 1;" ::: "memory")
#define CPA_WAIT0()   asm volatile("cp.async.wait_group 0;" ::: "memory")

__device__ __forceinline__ void ldsm4(uint32_t* r, uint32_t addr) {
    asm volatile("ldmatrix.sync.aligned.m8n8.x4.shared.b16 {%0,%1,%2,%3}, [%4];"
        : "=r"(r[0]), "=r"(r[1]), "=r"(r[2]), "=r"(r[3]) : "r"(addr));
}
__device__ __forceinline__ void mma_f16(float* c, const uint32_t* a,
                                        uint32_t b0, uint32_t b1) {
    asm volatile(
        "mma.sync.aligned.m16n8k16.row.col.f32.f16.f16.f32 "
        "{%0,%1,%2,%3}, {%4,%5,%6,%7}, {%8,%9}, {%0,%1,%2,%3};"
        : "+f"(c[0]), "+f"(c[1]), "+f"(c[2]), "+f"(c[3])
        : "r"(a[0]), "r"(a[1]), "r"(a[2]), "r"(a[3]), "r"(b0), "r"(b1));
}

// ---------------------------------------------------------------------------
// fp32 -> fp16 hi/lo split helpers (float4 in, 4xfp16 = 8B out per array)
// ---------------------------------------------------------------------------
__device__ __forceinline__ void split4h(const float4 v, uint2* hi4, uint2* lo4) {
    __half h[4], l[4];
    float f[4] = {v.x, v.y, v.z, v.w};
    #pragma unroll
    for (int q = 0; q < 4; q++) {
        h[q] = __float2half(f[q]);
        l[q] = __float2half(f[q] - __half2float(h[q]));
    }
    *hi4 = *reinterpret_cast<uint2*>(h);
    *lo4 = *reinterpret_cast<uint2*>(l);
}

__global__ __launch_bounds__(256) void splitX_kernel(const float* __restrict__ src) {
    int i = blockIdx.x * 256 + threadIdx.x;          // float4 index
    float4 v = reinterpret_cast<const float4*>(src)[i];
    uint2 h, l;
    split4h(v, &h, &l);
    reinterpret_cast<uint2*>(g_Xhi)[i] = h;
    reinterpret_cast<uint2*>(g_Xlo)[i] = l;
}

__global__ __launch_bounds__(256) void splitW_kernel(
    const float* __restrict__ w0, const float* __restrict__ w1,
    const float* __restrict__ w2, const float* __restrict__ w3) {
    const float* src = (blockIdx.y == 0) ? w0 : (blockIdx.y == 1) ? w1
                     : (blockIdx.y == 2) ? w2 : w3;
    int i = blockIdx.x * 256 + threadIdx.x;          // float4 index
    float4 v = reinterpret_cast<const float4*>(src)[i];
    __half h[4] = {__float2half(v.x), __float2half(v.y),
                   __float2half(v.z), __float2half(v.w)};
    reinterpret_cast<uint2*>(g_Wh[blockIdx.y])[i] = *reinterpret_cast<uint2*>(h);
}

// ---------------------------------------------------------------------------
// Split-fp16 HMMA GEMM: C[m,n] = sum_k A[m,k]*B[n,k]
// 2 MMAs per product: Ah*B + Al*B  (B rounded to fp16, err ~2^-11/sqrt3).
// Tile 128x128, K chunk 32, 8 warps (warp tile 32x64), 2 CTAs/SM.
// fused=1: projection (blockIdx.y = weight 0..2 -> silu/sigmoid/raw)
// fused=0: output GEMM (Wo, raw) into Cext.
// ---------------------------------------------------------------------------
__global__ __launch_bounds__(256, 2) void gemm_split(int fused, float* Cext) {
    extern __shared__ char smem[];
    const uint32_t sb = smem_u32(smem);
    const int tid  = threadIdx.x;
    const int lane = tid & 31;
    const int wid  = tid >> 5;
    const int wm   = wid & 3;      // 4 warps over M (32 rows each)
    const int wn   = wid >> 2;     // 2 warps over N (64 cols each)
    const int bn = blockIdx.x;
    const int w  = fused ? blockIdx.y : 3;
    const int bm = blockIdx.z;
    const int mode = fused ? ((w == 0) ? 0 : (w == 1) ? 1 : 2) : 2;

    const __half* Ah = fused ? g_Xhi : g_oHi;
    const __half* Al = fused ? g_Xlo : g_oLo;
    const __half* Bw = g_Wh[w];
    float* C = fused ? ((w == 0) ? g_bin : (w == 1) ? g_gate : g_g) : Cext;

    const size_t rowA = (size_t)bm * 128;
    const size_t rowB = (size_t)bn * 128;

    float acc[2][8][4];
    #pragma unroll
    for (int ma = 0; ma < 2; ma++)
        #pragma unroll
        for (int g = 0; g < 8; g++)
            #pragma unroll
            for (int q = 0; q < 4; q++) acc[ma][g][q] = 0.0f;

    // prefetch one K chunk (32 fp16 = 64B/row) into stage (c&1)
    // 1536 16B-chunks: [0,512) Ah, [512,1024) Al, [1024,1536) B
    auto prefetch = [&](int c) {
        const int k0 = c * KC;
        const uint32_t st = sb + (uint32_t)(c & 1) * STAGE;
        #pragma unroll
        for (int i = 0; i < 6; i++) {
            int slot = tid + i * 256;        // 0..1535
            int arr  = slot >> 9;            // 0=Ah, 1=Al, 2=B
            int s    = slot & 511;
            int row  = s >> 2, ch = s & 3;
            uint32_t so = swz64((uint32_t)row * 64 + ch * 16);
            if (arr < 2) {
                size_t gA = (rowA + row) * D_ + k0 + ch * 8;
                cpa16(st + arr * SUB + so, (arr ? Al : Ah) + gA);
            } else {
                size_t gB = (rowB + row) * D_ + k0 + ch * 8;
                cpa16(st + 2 * SUB + so, Bw + gB);
            }
        }
        CPA_COMMIT();
    };

    prefetch(0);
    prefetch(1);

    const int rowL = lane & 15;     // ldmatrix row within 16
    const int colL = lane >> 4;     // 16B chunk selector

    for (int c = 0; c < NKCH; c++) {
        if (c < NKCH - 1) { CPA_WAIT1(); } else { CPA_WAIT0(); }
        __syncthreads();

        const uint32_t st = sb + (uint32_t)(c & 1) * STAGE;
        #pragma unroll
        for (int ks = 0; ks < 2; ks++) {
            uint32_t ah[2][4], al[2][4];
            #pragma unroll
            for (int ma = 0; ma < 2; ma++) {
                uint32_t off = swz64((uint32_t)(wm * 32 + ma * 16 + rowL) * 64
                                     + ks * 32 + colL * 16);
                ldsm4(ah[ma], st + 0 * SUB + off);
                ldsm4(al[ma], st + 1 * SUB + off);
            }
            #pragma unroll
            for (int g16 = 0; g16 < 4; g16++) {
                uint32_t boff = swz64((uint32_t)(wn * 64 + g16 * 16 + rowL) * 64
                                      + ks * 32 + colL * 16);
                uint32_t bh[4];
                ldsm4(bh, st + 2 * SUB + boff);
                // wave 1: hi*B (4 independent accs)
                #pragma unroll
                for (int na = 0; na < 2; na++)
                    #pragma unroll
                    for (int ma = 0; ma < 2; ma++)
                        mma_f16(acc[ma][g16 * 2 + na], ah[ma], bh[na], bh[na + 2]);
                // wave 2: lo*B
                #pragma unroll
                for (int na = 0; na < 2; na++)
                    #pragma unroll
                    for (int ma = 0; ma < 2; ma++)
                        mma_f16(acc[ma][g16 * 2 + na], al[ma], bh[na], bh[na + 2]);
            }
        }
        __syncthreads();
        if (c + 2 < NKCH) prefetch(c + 2);
    }

    // epilogue: direct float2 stores with fused activation
    #pragma unroll
    for (int ma = 0; ma < 2; ma++) {
        #pragma unroll
        for (int g = 0; g < 8; g++) {
            int n = (int)rowB + wn * 64 + (g >> 1) * 16 + (g & 1) * 8 + (lane & 3) * 2;
            size_t m0 = rowA + wm * 32 + ma * 16 + (lane >> 2);
            #pragma unroll
            for (int h = 0; h < 2; h++) {           // h=0: rows, h=1: rows+8
                float v0 = acc[ma][g][h * 2 + 0];
                float v1 = acc[ma][g][h * 2 + 1];
                if (mode == 0)      { v0 = v0 * fsigmoid(v0); v1 = v1 * fsigmoid(v1); }
                else if (mode == 1) { v0 = fsigmoid(v0);      v1 = fsigmoid(v1); }
                float2 pr = make_float2(v0, v1);
                *reinterpret_cast<float2*>(&C[(m0 + h * 8) * D_ + n]) = pr;
            }
        }
    }
}

// ---------------------------------------------------------------------------
// Chunked linear-recurrence scan: h_t = a_t*h_{t-1} + b_t,  b_t = si*(1-a_t)
// ---------------------------------------------------------------------------
__global__ void scan_pass1_kernel() {
    int d = blockIdx.x * 256 + threadIdx.x;
    int c = blockIdx.y;
    int b = blockIdx.z;
    size_t base = ((size_t)b * L_ + (size_t)c * LCHUNK) * D_ + d;
    float a = 1.0f, h = 0.0f;
    #pragma unroll 4
    for (int t = 0; t < LCHUNK; t++) {
        float gt = g_gate[base + (size_t)t * D_];
        float si = g_bin [base + (size_t)t * D_];
        h = fmaf(gt, h, si * (1.0f - gt));
        a *= gt;
    }
    size_t idx = ((size_t)b * NCHUNK + c) * D_ + d;
    g_cA[idx] = a;
    g_cH[idx] = h;
}

__global__ void scan_pass2_kernel() {
    int d = blockIdx.x * 256 + threadIdx.x;
    int b = blockIdx.y;
    float h = 0.0f;
    #pragma unroll
    for (int c = 0; c < NCHUNK; c++) {
        size_t idx = ((size_t)b * NCHUNK + c) * D_ + d;
        g_pre[idx] = h;
        h = fmaf(g_cA[idx], h, g_cH[idx]);
    }
}

__global__ void scan_pass3_kernel() {
    int d = blockIdx.x * 256 + threadIdx.x;
    int c = blockIdx.y;
    int b = blockIdx.z;
    size_t base = ((size_t)b * L_ + (size_t)c * LCHUNK) * D_ + d;
    float h = g_pre[((size_t)b * NCHUNK + c) * D_ + d];
    #pragma unroll 4
    for (int t = 0; t < LCHUNK; t++) {
        size_t p = base + (size_t)t * D_;
        float gt = g_gate[p];
        float si = g_bin [p];
        h = fmaf(gt, h, si * (1.0f - gt));
        g_bin[p] = h;           // o overwrites silu(i) in place
    }
}

// ---------------------------------------------------------------------------
// RMSNorm(g)*weight*swish(o); writes fp16 hi/lo split for the output GEMM.
// ---------------------------------------------------------------------------
__global__ __launch_bounds__(256) void rms_gate_kernel(const float* __restrict__ gw) {
    const int m = blockIdx.x;
    const int tid = threadIdx.x;
    const float4* grow = reinterpret_cast<const float4*>(g_g  + (size_t)m * D_);
    const float4* orow = reinterpret_cast<const float4*>(g_bin + (size_t)m * D_);
    const float4* wrow = reinterpret_cast<const float4*>(gw);

    float4 gv[2];
    float ss = 0.0f;
    #pragma unroll
    for (int s = 0; s < 2; s++) {
        gv[s] = grow[tid + s * 256];
        ss += gv[s].x * gv[s].x + gv[s].y * gv[s].y
            + gv[s].z * gv[s].z + gv[s].w * gv[s].w;
    }

    __shared__ float sh[8];
    __shared__ float tot;
    int lane = tid & 31, wid = tid >> 5;
    #pragma unroll
    for (int o = 16; o > 0; o >>= 1) ss += __shfl_xor_sync(0xffffffffu, ss, o);
    if (lane == 0) sh[wid] = ss;
    __syncthreads();
    if (wid == 0) {
        float v = (lane < 8) ? sh[lane] : 0.0f;
        #pragma unroll
        for (int o = 4; o > 0; o >>= 1) v += __shfl_xor_sync(0xffffffffu, v, o);
        if (lane == 0) tot = v;
    }
    __syncthreads();

    float rms = rsqrtf(tot * (1.0f / D_) + 1e-5f);

    #pragma unroll
    for (int s = 0; s < 2; s++) {
        float4 o4 = orow[tid + s * 256];
        float4 w4 = wrow[tid + s * 256];
        float4 r;
        r.x = gv[s].x * rms * w4.x * (o4.x * fsigmoid(o4.x));
        r.y = gv[s].y * rms * w4.y * (o4.y * fsigmoid(o4.y));
        r.z = gv[s].z * rms * w4.z * (o4.z * fsigmoid(o4.z));
        r.w = gv[s].w * rms * w4.w * (o4.w * fsigmoid(o4.w));
        uint2 h, l;
        split4h(r, &h, &l);
        size_t b4 = (size_t)m * (D_ / 4) + tid + s * 256;
        reinterpret_cast<uint2*>(g_oHi)[b4] = h;
        reinterpret_cast<uint2*>(g_oLo)[b4] = l;
    }
}

// ---------------------------------------------------------------------------
extern "C" void kernel_launch(void* const* d_in, const int* in_sizes, int n_in,
                              void* d_out, int out_size)
{
    const float* X  = (const float*)d_in[0];
    const float* Wi = (const float*)d_in[1];
    const float* Wf = (const float*)d_in[2];
    const float* Wg = (const float*)d_in[3];
    const float* gw = (const float*)d_in[4];
    const float* Wo = (const float*)d_in[5];
    float* Y = (float*)d_out;

    static int smem_set = 0;
    if (!smem_set) {
        cudaFuncSetAttribute(gemm_split, cudaFuncAttributeMaxDynamicSharedMemorySize,
                             SMEM_TOTAL);
        smem_set = 1;
    }

    // fp32 -> fp16 splits
    splitX_kernel<<<(M_ * D_ / 4) / 256, 256>>>(X);
    splitW_kernel<<<dim3((D_ * D_ / 4) / 256, 4), 256>>>(Wi, Wf, Wg, Wo);

    // fused i/f/g projections: grid y = weight, z = M tile (L2 A-tile reuse)
    gemm_split<<<dim3(D_ / 128, 3, M_ / 128), 256, SMEM_TOTAL>>>(1, Y);

    scan_pass1_kernel<<<dim3(D_ / 256, NCHUNK, B_), 256>>>();
    scan_pass2_kernel<<<dim3(D_ / 256, B_), 256>>>();
    scan_pass3_kernel<<<dim3(D_ / 256, NCHUNK, B_), 256>>>();

    rms_gate_kernel<<<M_, 256>>>(gw);

    // out @ Wo^T -> Y
    gemm_split<<<dim3(D_ / 128, 1, M_ / 128), 256, SMEM_TOTAL>>>(0, Y);
}

// round 8
// speedup vs baseline: 2.2360x; 1.3922x over previous
#include <cuda_runtime.h>
#include <cuda_fp16.h>
#include <math.h>
#include <stdint.h>

#define B_ 4
#define L_ 4096
#define D_ 2048
#define M_ (B_*L_)            // 16384 rows
#define LCHUNK 128
#define NCHUNK (L_/LCHUNK)    // 32

// GEMM tiling: 128x128 tile, K chunk 32 fp16 (=64B row, SW64 swizzle)
#define KC 32
#define NKCH (D_/KC)          // 64
#define SUB 8192              // 128 rows * 64B

// ---------------- scratch (device globals; no allocation allowed) ----------
__device__ float g_gate[33554432];   // [M_, D_] sigmoid(f)
__device__ float g_bin [33554432];   // [M_, D_] silu(i); becomes o after scan
__device__ float g_g   [33554432];   // [M_, D_] g projection (raw)
__device__ float g_cA  [B_*NCHUNK*D_];
__device__ float g_cH  [B_*NCHUNK*D_];
__device__ float g_pre [B_*NCHUNK*D_];
__device__ __half g_Xhi[33554432], g_Xlo[33554432];
__device__ __half g_Wh[4][4194304];      // Wi,Wf,Wg,Wo (fp16 rounded)
__device__ __half g_o[33554432];         // rms-gated out (fp16)

__device__ __forceinline__ float fsigmoid(float x) {
    return 1.0f / (1.0f + __expf(-x));
}

// ---------------------------- PTX helpers ----------------------------------
__device__ __forceinline__ uint32_t smem_u32(const void* p) {
    uint32_t a;
    asm("{ .reg .u64 t; cvta.to.shared.u64 t, %1; cvt.u32.u64 %0, t; }"
        : "=r"(a) : "l"(p));
    return a;
}
__device__ __forceinline__ uint32_t swz64(uint32_t off) {
    return off ^ ((off >> 3) & 0x30);
}
__device__ __forceinline__ void cpa16(uint32_t s, const void* g) {
    asm volatile("cp.async.cg.shared.global [%0], [%1], 16;" :: "r"(s), "l"(g));
}
#define CPA_COMMIT()  asm volatile("cp.async.commit_group;" ::: "memory")
#define CPA_WAIT1()   asm volatile("cp.async.wait_group 1;" ::: "memory")
#define CPA_WAIT0()   asm volatile("cp.async.wait_group 0;" ::: "memory")

__device__ __forceinline__ void ldsm4(uint32_t* r, uint32_t addr) {
    asm volatile("ldmatrix.sync.aligned.m8n8.x4.shared.b16 {%0,%1,%2,%3}, [%4];"
        : "=r"(r[0]), "=r"(r[1]), "=r"(r[2]), "=r"(r[3]) : "r"(addr));
}
__device__ __forceinline__ void mma_f16(float* c, const uint32_t* a,
                                        uint32_t b0, uint32_t b1) {
    asm volatile(
        "mma.sync.aligned.m16n8k16.row.col.f32.f16.f16.f32 "
        "{%0,%1,%2,%3}, {%4,%5,%6,%7}, {%8,%9}, {%0,%1,%2,%3};"
        : "+f"(c[0]), "+f"(c[1]), "+f"(c[2]), "+f"(c[3])
        : "r"(a[0]), "r"(a[1]), "r"(a[2]), "r"(a[3]), "r"(b0), "r"(b1));
}

// ---------------------------------------------------------------------------
// fp32 -> fp16 splits
// ---------------------------------------------------------------------------
__device__ __forceinline__ void split4h(const float4 v, uint2* hi4, uint2* lo4) {
    __half h[4], l[4];
    float f[4] = {v.x, v.y, v.z, v.w};
    #pragma unroll
    for (int q = 0; q < 4; q++) {
        h[q] = __float2half(f[q]);
        l[q] = __float2half(f[q] - __half2float(h[q]));
    }
    *hi4 = *reinterpret_cast<uint2*>(h);
    *lo4 = *reinterpret_cast<uint2*>(l);
}

__global__ __launch_bounds__(256) void splitX_kernel(const float* __restrict__ src) {
    int i = blockIdx.x * 256 + threadIdx.x;          // float4 index
    float4 v = reinterpret_cast<const float4*>(src)[i];
    uint2 h, l;
    split4h(v, &h, &l);
    reinterpret_cast<uint2*>(g_Xhi)[i] = h;
    reinterpret_cast<uint2*>(g_Xlo)[i] = l;
}

__global__ __launch_bounds__(256) void splitW_kernel(
    const float* __restrict__ w0, const float* __restrict__ w1,
    const float* __restrict__ w2, const float* __restrict__ w3) {
    const float* src = (blockIdx.y == 0) ? w0 : (blockIdx.y == 1) ? w1
                     : (blockIdx.y == 2) ? w2 : w3;
    int i = blockIdx.x * 256 + threadIdx.x;          // float4 index
    float4 v = reinterpret_cast<const float4*>(src)[i];
    __half h[4] = {__float2half(v.x), __float2half(v.y),
                   __float2half(v.z), __float2half(v.w)};
    reinterpret_cast<uint2*>(g_Wh[blockIdx.y])[i] = *reinterpret_cast<uint2*>(h);
}

// ---------------------------------------------------------------------------
// fp16 HMMA GEMM: C[m,n] = sum_k A[m,k]*B[n,k]
// SA=true : 2 MMAs per product (A split hi/lo) -- used for the f projection.
// SA=false: 1 MMA  per product (A fp16)        -- i/g projections, output.
// Tile 128x128, K chunk 32, 8 warps (warp tile 32x64), 2 CTAs/SM.
// which: 0 = f (Wf, sigmoid -> g_gate)
//        1 = i/g fused (y=0: Wi, silu -> g_bin ; y=1: Wg, raw -> g_g)
//        2 = output (Wo, raw -> Cext)
// ---------------------------------------------------------------------------
template <bool SA>
__global__ __launch_bounds__(256, 2) void gemm_t(int which, float* Cext) {
    extern __shared__ char smem[];
    const uint32_t sb = smem_u32(smem);
    const int NSUB  = SA ? 3 : 2;           // Ah[,Al],B
    const int STAGE = NSUB * SUB;
    const int tid  = threadIdx.x;
    const int lane = tid & 31;
    const int wid  = tid >> 5;
    const int wm   = wid & 3;      // 4 warps over M (32 rows each)
    const int wn   = wid >> 2;     // 2 warps over N (64 cols each)
    const int bn = blockIdx.x;
    const int bm = blockIdx.z;

    const __half *Ah, *Al = nullptr, *Bw;
    float* C;
    int mode;                                    // 0 silu, 1 sigmoid, 2 raw
    if (which == 0)      { Ah = g_Xhi; Al = g_Xlo; Bw = g_Wh[1]; C = g_gate; mode = 1; }
    else if (which == 1) {
        Ah = g_Xhi;
        if (blockIdx.y == 0) { Bw = g_Wh[0]; C = g_bin; mode = 0; }
        else                 { Bw = g_Wh[2]; C = g_g;   mode = 2; }
    } else               { Ah = g_o;   Bw = g_Wh[3]; C = Cext;  mode = 2; }

    const size_t rowA = (size_t)bm * 128;
    const size_t rowB = (size_t)bn * 128;

    float acc[2][8][4];
    #pragma unroll
    for (int ma = 0; ma < 2; ma++)
        #pragma unroll
        for (int g = 0; g < 8; g++)
            #pragma unroll
            for (int q = 0; q < 4; q++) acc[ma][g][q] = 0.0f;

    // prefetch one K chunk (32 fp16 = 64B/row) into stage (c&1)
    // 512 16B-chunks per sub-buffer: [A hi][A lo (SA)][B]
    auto prefetch = [&](int c) {
        const int k0 = c * KC;
        const uint32_t st = sb + (uint32_t)(c & 1) * STAGE;
        #pragma unroll
        for (int i = 0; i < (SA ? 6 : 4); i++) {
            int slot = tid + i * 256;
            int arr  = slot >> 9;            // sub-buffer index
            int s    = slot & 511;
            int row  = s >> 2, ch = s & 3;
            uint32_t so = swz64((uint32_t)row * 64 + ch * 16);
            if (arr < NSUB - 1) {
                size_t gA = (rowA + row) * D_ + k0 + ch * 8;
                cpa16(st + arr * SUB + so, ((arr == 1) ? Al : Ah) + gA);
            } else {
                size_t gB = (rowB + row) * D_ + k0 + ch * 8;
                cpa16(st + (NSUB - 1) * SUB + so, Bw + gB);
            }
        }
        CPA_COMMIT();
    };

    prefetch(0);
    prefetch(1);

    const int rowL = lane & 15;     // ldmatrix row within 16
    const int colL = lane >> 4;     // 16B chunk selector

    for (int c = 0; c < NKCH; c++) {
        if (c < NKCH - 1) { CPA_WAIT1(); } else { CPA_WAIT0(); }
        __syncthreads();

        const uint32_t st = sb + (uint32_t)(c & 1) * STAGE;
        #pragma unroll
        for (int ks = 0; ks < 2; ks++) {
            uint32_t ah[2][4], al[2][4];
            #pragma unroll
            for (int ma = 0; ma < 2; ma++) {
                uint32_t off = swz64((uint32_t)(wm * 32 + ma * 16 + rowL) * 64
                                     + ks * 32 + colL * 16);
                ldsm4(ah[ma], st + 0 * SUB + off);
                if (SA) ldsm4(al[ma], st + 1 * SUB + off);
            }
            #pragma unroll
            for (int g16 = 0; g16 < 4; g16++) {
                uint32_t boff = swz64((uint32_t)(wn * 64 + g16 * 16 + rowL) * 64
                                      + ks * 32 + colL * 16);
                uint32_t bh[4];
                ldsm4(bh, st + (NSUB - 1) * SUB + boff);
                #pragma unroll
                for (int na = 0; na < 2; na++)
                    #pragma unroll
                    for (int ma = 0; ma < 2; ma++)
                        mma_f16(acc[ma][g16 * 2 + na], ah[ma], bh[na], bh[na + 2]);
                if (SA) {
                    #pragma unroll
                    for (int na = 0; na < 2; na++)
                        #pragma unroll
                        for (int ma = 0; ma < 2; ma++)
                            mma_f16(acc[ma][g16 * 2 + na], al[ma], bh[na], bh[na + 2]);
                }
            }
        }
        __syncthreads();
        if (c + 2 < NKCH) prefetch(c + 2);
    }

    // epilogue: direct float2 stores with fused activation
    #pragma unroll
    for (int ma = 0; ma < 2; ma++) {
        #pragma unroll
        for (int g = 0; g < 8; g++) {
            int n = (int)rowB + wn * 64 + (g >> 1) * 16 + (g & 1) * 8 + (lane & 3) * 2;
            size_t m0 = rowA + wm * 32 + ma * 16 + (lane >> 2);
            #pragma unroll
            for (int h = 0; h < 2; h++) {           // h=0: rows, h=1: rows+8
                float v0 = acc[ma][g][h * 2 + 0];
                float v1 = acc[ma][g][h * 2 + 1];
                if (mode == 0)      { v0 = v0 * fsigmoid(v0); v1 = v1 * fsigmoid(v1); }
                else if (mode == 1) { v0 = fsigmoid(v0);      v1 = fsigmoid(v1); }
                float2 pr = make_float2(v0, v1);
                *reinterpret_cast<float2*>(&C[(m0 + h * 8) * D_ + n]) = pr;
            }
        }
    }
}

// ---------------------------------------------------------------------------
// Chunked linear-recurrence scan: h_t = a_t*h_{t-1} + b_t,  b_t = si*(1-a_t)
// ---------------------------------------------------------------------------
__global__ void scan_pass1_kernel() {
    int d = blockIdx.x * 256 + threadIdx.x;
    int c = blockIdx.y;
    int b = blockIdx.z;
    size_t base = ((size_t)b * L_ + (size_t)c * LCHUNK) * D_ + d;
    float a = 1.0f, h = 0.0f;
    #pragma unroll 4
    for (int t = 0; t < LCHUNK; t++) {
        float gt = g_gate[base + (size_t)t * D_];
        float si = g_bin [base + (size_t)t * D_];
        h = fmaf(gt, h, si * (1.0f - gt));
        a *= gt;
    }
    size_t idx = ((size_t)b * NCHUNK + c) * D_ + d;
    g_cA[idx] = a;
    g_cH[idx] = h;
}

__global__ void scan_pass2_kernel() {
    int d = blockIdx.x * 256 + threadIdx.x;
    int b = blockIdx.y;
    float h = 0.0f;
    #pragma unroll
    for (int c = 0; c < NCHUNK; c++) {
        size_t idx = ((size_t)b * NCHUNK + c) * D_ + d;
        g_pre[idx] = h;
        h = fmaf(g_cA[idx], h, g_cH[idx]);
    }
}

__global__ void scan_pass3_kernel() {
    int d = blockIdx.x * 256 + threadIdx.x;
    int c = blockIdx.y;
    int b = blockIdx.z;
    size_t base = ((size_t)b * L_ + (size_t)c * LCHUNK) * D_ + d;
    float h = g_pre[((size_t)b * NCHUNK + c) * D_ + d];
    #pragma unroll 4
    for (int t = 0; t < LCHUNK; t++) {
        size_t p = base + (size_t)t * D_;
        float gt = g_gate[p];
        float si = g_bin [p];
        h = fmaf(gt, h, si * (1.0f - gt));
        g_bin[p] = h;           // o overwrites silu(i) in place
    }
}

// ---------------------------------------------------------------------------
// RMSNorm(g)*weight*swish(o); writes fp16 for the output GEMM.
// ---------------------------------------------------------------------------
__global__ __launch_bounds__(256) void rms_gate_kernel(const float* __restrict__ gw) {
    const int m = blockIdx.x;
    const int tid = threadIdx.x;
    const float4* grow = reinterpret_cast<const float4*>(g_g  + (size_t)m * D_);
    const float4* orow = reinterpret_cast<const float4*>(g_bin + (size_t)m * D_);
    const float4* wrow = reinterpret_cast<const float4*>(gw);

    float4 gv[2];
    float ss = 0.0f;
    #pragma unroll
    for (int s = 0; s < 2; s++) {
        gv[s] = grow[tid + s * 256];
        ss += gv[s].x * gv[s].x + gv[s].y * gv[s].y
            + gv[s].z * gv[s].z + gv[s].w * gv[s].w;
    }

    __shared__ float sh[8];
    __shared__ float tot;
    int lane = tid & 31, wid = tid >> 5;
    #pragma unroll
    for (int o = 16; o > 0; o >>= 1) ss += __shfl_xor_sync(0xffffffffu, ss, o);
    if (lane == 0) sh[wid] = ss;
    __syncthreads();
    if (wid == 0) {
        float v = (lane < 8) ? sh[lane] : 0.0f;
        #pragma unroll
        for (int o = 4; o > 0; o >>= 1) v += __shfl_xor_sync(0xffffffffu, v, o);
        if (lane == 0) tot = v;
    }
    __syncthreads();

    float rms = rsqrtf(tot * (1.0f / D_) + 1e-5f);

    #pragma unroll
    for (int s = 0; s < 2; s++) {
        float4 o4 = orow[tid + s * 256];
        float4 w4 = wrow[tid + s * 256];
        __half h[4];
        h[0] = __float2half(gv[s].x * rms * w4.x * (o4.x * fsigmoid(o4.x)));
        h[1] = __float2half(gv[s].y * rms * w4.y * (o4.y * fsigmoid(o4.y)));
        h[2] = __float2half(gv[s].z * rms * w4.z * (o4.z * fsigmoid(o4.z)));
        h[3] = __float2half(gv[s].w * rms * w4.w * (o4.w * fsigmoid(o4.w)));
        size_t b4 = (size_t)m * (D_ / 4) + tid + s * 256;
        reinterpret_cast<uint2*>(g_o)[b4] = *reinterpret_cast<uint2*>(h);
    }
}

// ---------------------------------------------------------------------------
extern "C" void kernel_launch(void* const* d_in, const int* in_sizes, int n_in,
                              void* d_out, int out_size)
{
    const float* X  = (const float*)d_in[0];
    const float* Wi = (const float*)d_in[1];
    const float* Wf = (const float*)d_in[2];
    const float* Wg = (const float*)d_in[3];
    const float* gw = (const float*)d_in[4];
    const float* Wo = (const float*)d_in[5];
    float* Y = (float*)d_out;

    // fp32 -> fp16 splits
    splitX_kernel<<<(M_ * D_ / 4) / 256, 256>>>(X);
    splitW_kernel<<<dim3((D_ * D_ / 4) / 256, 4), 256>>>(Wi, Wf, Wg, Wo);

    // f projection (2-MMA A-split, protects the scan gate)
    gemm_t<true><<<dim3(D_ / 128, 1, M_ / 128), 256, 2 * 3 * SUB>>>(0, Y);
    // i + g projections (1-MMA)
    gemm_t<false><<<dim3(D_ / 128, 2, M_ / 128), 256, 2 * 2 * SUB>>>(1, Y);

    scan_pass1_kernel<<<dim3(D_ / 256, NCHUNK, B_), 256>>>();
    scan_pass2_kernel<<<dim3(D_ / 256, B_), 256>>>();
    scan_pass3_kernel<<<dim3(D_ / 256, NCHUNK, B_), 256>>>();

    rms_gate_kernel<<<M_, 256>>>(gw);

    // out @ Wo^T -> Y (1-MMA)
    gemm_t<false><<<dim3(D_ / 128, 1, M_ / 128), 256, 2 * 2 * SUB>>>(2, Y);
}

// round 9
// speedup vs baseline: 2.5571x; 1.1436x over previous
#include <cuda_runtime.h>
#include <cuda_fp16.h>
#include <math.h>
#include <stdint.h>

#define B_ 4
#define L_ 4096
#define D_ 2048
#define M_ (B_*L_)            // 16384 rows
#define LCHUNK 128
#define NCHUNK (L_/LCHUNK)    // 32

// GEMM tiling: 128x128 tile, K chunk 64 fp16 (=128B row, SW128 swizzle)
#define KC 64
#define NKCH (D_/KC)          // 32
#define SUB 16384             // 128 rows * 128B

// ---------------- scratch (device globals; no allocation allowed) ----------
__device__ float g_gate[33554432];   // [M_, D_] sigmoid(f)
__device__ float g_bin [33554432];   // [M_, D_] silu(i); becomes o after scan
__device__ float g_g   [33554432];   // [M_, D_] g projection (raw)
__device__ float g_cA  [B_*NCHUNK*D_];
__device__ float g_cH  [B_*NCHUNK*D_];
__device__ float g_pre [B_*NCHUNK*D_];
__device__ __half g_Xhi[33554432], g_Xlo[33554432];
__device__ __half g_Wh[4][4194304];      // Wi,Wf,Wg,Wo (fp16 rounded)
__device__ __half g_o[33554432];         // rms-gated out (fp16)

__device__ __forceinline__ float fsigmoid(float x) {
    return 1.0f / (1.0f + __expf(-x));
}

// ---------------------------- PTX helpers ----------------------------------
__device__ __forceinline__ uint32_t smem_u32(const void* p) {
    uint32_t a;
    asm("{ .reg .u64 t; cvta.to.shared.u64 t, %1; cvt.u32.u64 %0, t; }"
        : "=r"(a) : "l"(p));
    return a;
}
__device__ __forceinline__ uint32_t swz128(uint32_t off) {
    return off ^ ((off >> 3) & 0x70);
}
__device__ __forceinline__ void cpa16(uint32_t s, const void* g) {
    asm volatile("cp.async.cg.shared.global [%0], [%1], 16;" :: "r"(s), "l"(g));
}
#define CPA_COMMIT()  asm volatile("cp.async.commit_group;" ::: "memory")
#define CPA_WAIT1()   asm volatile("cp.async.wait_group 1;" ::: "memory")
#define CPA_WAIT0()   asm volatile("cp.async.wait_group 0;" ::: "memory")

__device__ __forceinline__ void ldsm4(uint32_t* r, uint32_t addr) {
    asm volatile("ldmatrix.sync.aligned.m8n8.x4.shared.b16 {%0,%1,%2,%3}, [%4];"
        : "=r"(r[0]), "=r"(r[1]), "=r"(r[2]), "=r"(r[3]) : "r"(addr));
}
__device__ __forceinline__ void mma_f16(float* c, const uint32_t* a,
                                        uint32_t b0, uint32_t b1) {
    asm volatile(
        "mma.sync.aligned.m16n8k16.row.col.f32.f16.f16.f32 "
        "{%0,%1,%2,%3}, {%4,%5,%6,%7}, {%8,%9}, {%0,%1,%2,%3};"
        : "+f"(c[0]), "+f"(c[1]), "+f"(c[2]), "+f"(c[3])
        : "r"(a[0]), "r"(a[1]), "r"(a[2]), "r"(a[3]), "r"(b0), "r"(b1));
}

// ---------------------------------------------------------------------------
// fp32 -> fp16 splits
// ---------------------------------------------------------------------------
__device__ __forceinline__ void split4h(const float4 v, uint2* hi4, uint2* lo4) {
    __half h[4], l[4];
    float f[4] = {v.x, v.y, v.z, v.w};
    #pragma unroll
    for (int q = 0; q < 4; q++) {
        h[q] = __float2half(f[q]);
        l[q] = __float2half(f[q] - __half2float(h[q]));
    }
    *hi4 = *reinterpret_cast<uint2*>(h);
    *lo4 = *reinterpret_cast<uint2*>(l);
}

__global__ __launch_bounds__(256) void splitX_kernel(const float* __restrict__ src) {
    int i = blockIdx.x * 256 + threadIdx.x;          // float4 index
    float4 v = reinterpret_cast<const float4*>(src)[i];
    uint2 h, l;
    split4h(v, &h, &l);
    reinterpret_cast<uint2*>(g_Xhi)[i] = h;
    reinterpret_cast<uint2*>(g_Xlo)[i] = l;
}

__global__ __launch_bounds__(256) void splitW_kernel(
    const float* __restrict__ w0, const float* __restrict__ w1,
    const float* __restrict__ w2, const float* __restrict__ w3) {
    const float* src = (blockIdx.y == 0) ? w0 : (blockIdx.y == 1) ? w1
                     : (blockIdx.y == 2) ? w2 : w3;
    int i = blockIdx.x * 256 + threadIdx.x;          // float4 index
    float4 v = reinterpret_cast<const float4*>(src)[i];
    __half h[4] = {__float2half(v.x), __float2half(v.y),
                   __float2half(v.z), __float2half(v.w)};
    reinterpret_cast<uint2*>(g_Wh[blockIdx.y])[i] = *reinterpret_cast<uint2*>(h);
}

// ---------------------------------------------------------------------------
// fp16 HMMA GEMM: C[m,n] = sum_k A[m,k]*B[n,k]
// SA=true : 2 MMAs per product (A split hi/lo) -- f projection.
// SA=false: 1 MMA  per product (A fp16)        -- i/g projections, output.
// Tile 128x128, K chunk 64, 8 warps (warp tile 32x64), 2 CTAs/SM.
// which: 0 = f (Wf, sigmoid -> g_gate)
//        1 = i/g fused (y=0: Wi, silu -> g_bin ; y=1: Wg, raw -> g_g)
//        2 = output (Wo, raw -> Cext)
// ---------------------------------------------------------------------------
template <bool SA>
__global__ __launch_bounds__(256, 2) void gemm_t(int which, float* Cext) {
    extern __shared__ char smem[];
    const uint32_t sb = smem_u32(smem);
    const int NSUB  = SA ? 3 : 2;           // Ah[,Al],B
    const int STAGE = NSUB * SUB;
    const int tid  = threadIdx.x;
    const int lane = tid & 31;
    const int wid  = tid >> 5;
    const int wm   = wid & 3;      // 4 warps over M (32 rows each)
    const int wn   = wid >> 2;     // 2 warps over N (64 cols each)
    const int bn = blockIdx.x;
    const int bm = blockIdx.z;

    const __half *Ah, *Al = nullptr, *Bw;
    float* C;
    int mode;                                    // 0 silu, 1 sigmoid, 2 raw
    if (which == 0)      { Ah = g_Xhi; Al = g_Xlo; Bw = g_Wh[1]; C = g_gate; mode = 1; }
    else if (which == 1) {
        Ah = g_Xhi;
        if (blockIdx.y == 0) { Bw = g_Wh[0]; C = g_bin; mode = 0; }
        else                 { Bw = g_Wh[2]; C = g_g;   mode = 2; }
    } else               { Ah = g_o;   Bw = g_Wh[3]; C = Cext;  mode = 2; }

    const size_t rowA = (size_t)bm * 128;
    const size_t rowB = (size_t)bn * 128;

    float acc[2][8][4];
    #pragma unroll
    for (int ma = 0; ma < 2; ma++)
        #pragma unroll
        for (int g = 0; g < 8; g++)
            #pragma unroll
            for (int q = 0; q < 4; q++) acc[ma][g][q] = 0.0f;

    // strength-reduced prefetch state: one base pointer + base smem offset
    // per sub-buffer; within a sub-buffer the 4 per-thread loads are 32 rows
    // apart (32*D_ elems global, +4096B smem; swz128 invariant under +4096).
    const int prow = tid >> 3;            // 0..31
    const int pch  = tid & 7;             // 16B chunk in 128B row
    const uint32_t so0 = swz128((uint32_t)prow * 128 + pch * 16);
    const __half* pA = Ah + (rowA + prow) * D_ + pch * 8;
    const __half* pL = SA ? (Al + (rowA + prow) * D_ + pch * 8) : nullptr;
    const __half* pB = Bw + (rowB + prow) * D_ + pch * 8;

    auto prefetch = [&](int c) {
        const uint32_t st = sb + (uint32_t)(c & 1) * STAGE;
        #pragma unroll
        for (int r = 0; r < 4; r++) {
            uint32_t so = so0 + r * 4096;
            size_t   go = (size_t)r * 32 * D_;
            cpa16(st + so, pA + go);
            if (SA) cpa16(st + SUB + so, pL + go);
            cpa16(st + (NSUB - 1) * SUB + so, pB + go);
        }
        pA += KC; pB += KC; if (SA) pL += KC;
        CPA_COMMIT();
    };

    prefetch(0);
    prefetch(1);

    // hoisted ldsm row bases (swizzle applied per use: 3 ALU ops)
    const int rowL = lane & 15;
    const int colL = lane >> 4;
    uint32_t arb[2], brb[4];
    #pragma unroll
    for (int ma = 0; ma < 2; ma++)
        arb[ma] = (uint32_t)(wm * 32 + ma * 16 + rowL) * 128 + colL * 16;
    #pragma unroll
    for (int g16 = 0; g16 < 4; g16++)
        brb[g16] = (uint32_t)(wn * 64 + g16 * 16 + rowL) * 128 + colL * 16;

    for (int c = 0; c < NKCH; c++) {
        if (c < NKCH - 1) { CPA_WAIT1(); } else { CPA_WAIT0(); }
        __syncthreads();

        const uint32_t st = sb + (uint32_t)(c & 1) * STAGE;
        #pragma unroll
        for (int ks = 0; ks < 4; ks++) {
            uint32_t ah[2][4], al[2][4];
            #pragma unroll
            for (int ma = 0; ma < 2; ma++) {
                uint32_t off = swz128(arb[ma] + ks * 32);
                ldsm4(ah[ma], st + off);
                if (SA) ldsm4(al[ma], st + SUB + off);
            }
            #pragma unroll
            for (int g16 = 0; g16 < 4; g16++) {
                uint32_t bh[4];
                ldsm4(bh, st + (NSUB - 1) * SUB + swz128(brb[g16] + ks * 32));
                #pragma unroll
                for (int na = 0; na < 2; na++)
                    #pragma unroll
                    for (int ma = 0; ma < 2; ma++)
                        mma_f16(acc[ma][g16 * 2 + na], ah[ma], bh[na], bh[na + 2]);
                if (SA) {
                    #pragma unroll
                    for (int na = 0; na < 2; na++)
                        #pragma unroll
                        for (int ma = 0; ma < 2; ma++)
                            mma_f16(acc[ma][g16 * 2 + na], al[ma], bh[na], bh[na + 2]);
                }
            }
        }
        __syncthreads();
        if (c + 2 < NKCH) prefetch(c + 2);
    }

    // epilogue: direct float2 stores with fused activation
    #pragma unroll
    for (int ma = 0; ma < 2; ma++) {
        #pragma unroll
        for (int g = 0; g < 8; g++) {
            int n = (int)rowB + wn * 64 + (g >> 1) * 16 + (g & 1) * 8 + (lane & 3) * 2;
            size_t m0 = rowA + wm * 32 + ma * 16 + (lane >> 2);
            #pragma unroll
            for (int h = 0; h < 2; h++) {           // h=0: rows, h=1: rows+8
                float v0 = acc[ma][g][h * 2 + 0];
                float v1 = acc[ma][g][h * 2 + 1];
                if (mode == 0)      { v0 = v0 * fsigmoid(v0); v1 = v1 * fsigmoid(v1); }
                else if (mode == 1) { v0 = fsigmoid(v0);      v1 = fsigmoid(v1); }
                float2 pr = make_float2(v0, v1);
                *reinterpret_cast<float2*>(&C[(m0 + h * 8) * D_ + n]) = pr;
            }
        }
    }
}

// ---------------------------------------------------------------------------
// Chunked linear-recurrence scan: h_t = a_t*h_{t-1} + b_t,  b_t = si*(1-a_t)
// ---------------------------------------------------------------------------
__global__ void scan_pass1_kernel() {
    int d = blockIdx.x * 256 + threadIdx.x;
    int c = blockIdx.y;
    int b = blockIdx.z;
    size_t base = ((size_t)b * L_ + (size_t)c * LCHUNK) * D_ + d;
    float a = 1.0f, h = 0.0f;
    #pragma unroll 4
    for (int t = 0; t < LCHUNK; t++) {
        float gt = g_gate[base + (size_t)t * D_];
        float si = g_bin [base + (size_t)t * D_];
        h = fmaf(gt, h, si * (1.0f - gt));
        a *= gt;
    }
    size_t idx = ((size_t)b * NCHUNK + c) * D_ + d;
    g_cA[idx] = a;
    g_cH[idx] = h;
}

__global__ void scan_pass2_kernel() {
    int d = blockIdx.x * 256 + threadIdx.x;
    int b = blockIdx.y;
    float h = 0.0f;
    #pragma unroll
    for (int c = 0; c < NCHUNK; c++) {
        size_t idx = ((size_t)b * NCHUNK + c) * D_ + d;
        g_pre[idx] = h;
        h = fmaf(g_cA[idx], h, g_cH[idx]);
    }
}

__global__ void scan_pass3_kernel() {
    int d = blockIdx.x * 256 + threadIdx.x;
    int c = blockIdx.y;
    int b = blockIdx.z;
    size_t base = ((size_t)b * L_ + (size_t)c * LCHUNK) * D_ + d;
    float h = g_pre[((size_t)b * NCHUNK + c) * D_ + d];
    #pragma unroll 4
    for (int t = 0; t < LCHUNK; t++) {
        size_t p = base + (size_t)t * D_;
        float gt = g_gate[p];
        float si = g_bin [p];
        h = fmaf(gt, h, si * (1.0f - gt));
        g_bin[p] = h;           // o overwrites silu(i) in place
    }
}

// ---------------------------------------------------------------------------
// RMSNorm(g)*weight*swish(o); writes fp16 for the output GEMM.
// ---------------------------------------------------------------------------
__global__ __launch_bounds__(256) void rms_gate_kernel(const float* __restrict__ gw) {
    const int m = blockIdx.x;
    const int tid = threadIdx.x;
    const float4* grow = reinterpret_cast<const float4*>(g_g  + (size_t)m * D_);
    const float4* orow = reinterpret_cast<const float4*>(g_bin + (size_t)m * D_);
    const float4* wrow = reinterpret_cast<const float4*>(gw);

    float4 gv[2];
    float ss = 0.0f;
    #pragma unroll
    for (int s = 0; s < 2; s++) {
        gv[s] = grow[tid + s * 256];
        ss += gv[s].x * gv[s].x + gv[s].y * gv[s].y
            + gv[s].z * gv[s].z + gv[s].w * gv[s].w;
    }

    __shared__ float sh[8];
    __shared__ float tot;
    int lane = tid & 31, wid = tid >> 5;
    #pragma unroll
    for (int o = 16; o > 0; o >>= 1) ss += __shfl_xor_sync(0xffffffffu, ss, o);
    if (lane == 0) sh[wid] = ss;
    __syncthreads();
    if (wid == 0) {
        float v = (lane < 8) ? sh[lane] : 0.0f;
        #pragma unroll
        for (int o = 4; o > 0; o >>= 1) v += __shfl_xor_sync(0xffffffffu, v, o);
        if (lane == 0) tot = v;
    }
    __syncthreads();

    float rms = rsqrtf(tot * (1.0f / D_) + 1e-5f);

    #pragma unroll
    for (int s = 0; s < 2; s++) {
        float4 o4 = orow[tid + s * 256];
        float4 w4 = wrow[tid + s * 256];
        __half h[4];
        h[0] = __float2half(gv[s].x * rms * w4.x * (o4.x * fsigmoid(o4.x)));
        h[1] = __float2half(gv[s].y * rms * w4.y * (o4.y * fsigmoid(o4.y)));
        h[2] = __float2half(gv[s].z * rms * w4.z * (o4.z * fsigmoid(o4.z)));
        h[3] = __float2half(gv[s].w * rms * w4.w * (o4.w * fsigmoid(o4.w)));
        size_t b4 = (size_t)m * (D_ / 4) + tid + s * 256;
        reinterpret_cast<uint2*>(g_o)[b4] = *reinterpret_cast<uint2*>(h);
    }
}

// ---------------------------------------------------------------------------
extern "C" void kernel_launch(void* const* d_in, const int* in_sizes, int n_in,
                              void* d_out, int out_size)
{
    const float* X  = (const float*)d_in[0];
    const float* Wi = (const float*)d_in[1];
    const float* Wf = (const float*)d_in[2];
    const float* Wg = (const float*)d_in[3];
    const float* gw = (const float*)d_in[4];
    const float* Wo = (const float*)d_in[5];
    float* Y = (float*)d_out;

    static int smem_set = 0;
    if (!smem_set) {
        cudaFuncSetAttribute(gemm_t<true>,
            cudaFuncAttributeMaxDynamicSharedMemorySize, 2 * 3 * SUB);
        cudaFuncSetAttribute(gemm_t<false>,
            cudaFuncAttributeMaxDynamicSharedMemorySize, 2 * 2 * SUB);
        smem_set = 1;
    }

    // fp32 -> fp16 splits
    splitX_kernel<<<(M_ * D_ / 4) / 256, 256>>>(X);
    splitW_kernel<<<dim3((D_ * D_ / 4) / 256, 4), 256>>>(Wi, Wf, Wg, Wo);

    // f projection (2-MMA A-split, protects the scan gate)
    gemm_t<true><<<dim3(D_ / 128, 1, M_ / 128), 256, 2 * 3 * SUB>>>(0, Y);
    // i + g projections (1-MMA)
    gemm_t<false><<<dim3(D_ / 128, 2, M_ / 128), 256, 2 * 2 * SUB>>>(1, Y);

    scan_pass1_kernel<<<dim3(D_ / 256, NCHUNK, B_), 256>>>();
    scan_pass2_kernel<<<dim3(D_ / 256, B_), 256>>>();
    scan_pass3_kernel<<<dim3(D_ / 256, NCHUNK, B_), 256>>>();

    rms_gate_kernel<<<M_, 256>>>(gw);

    // out @ Wo^T -> Y (1-MMA)
    gemm_t<false><<<dim3(D_ / 128, 1, M_ / 128), 256, 2 * 2 * SUB>>>(2, Y);
}

// round 10
// speedup vs baseline: 3.0391x; 1.1885x over previous
#include <cuda_runtime.h>
#include <cuda_fp16.h>
#include <math.h>
#include <stdint.h>

#define B_ 4
#define L_ 4096
#define D_ 2048
#define M_ (B_*L_)            // 16384 rows
#define LCHUNK 128
#define NCHUNK (L_/LCHUNK)    // 32

// GEMM tiling: 128x128 tile, K chunk 64 fp16 (=128B row, SW128 swizzle)
#define KC 64
#define NKCH (D_/KC)          // 32
#define SUB 16384             // 128 rows * 128B
#define STAGE (2*SUB)         // A, B = 32KB
#define SMEM_TOTAL (2*STAGE)  // 64KB double buffered -> 2 CTAs/SM

// ---------------- scratch (device globals; no allocation allowed) ----------
__device__ float g_gate[33554432];   // [M_, D_] sigmoid(f)
__device__ float g_bin [33554432];   // [M_, D_] silu(i); becomes o after scan
__device__ float g_g   [33554432];   // [M_, D_] g projection (raw)
__device__ float g_cA  [B_*NCHUNK*D_];
__device__ float g_cH  [B_*NCHUNK*D_];
__device__ float g_pre [B_*NCHUNK*D_];
__device__ __half g_Xh[33554432];        // X (fp16 rounded)
__device__ __half g_Wh[4][4194304];      // Wi,Wf,Wg,Wo (fp16 rounded)
__device__ __half g_o[33554432];         // rms-gated out (fp16)

__device__ __forceinline__ float fsigmoid(float x) {
    return 1.0f / (1.0f + __expf(-x));
}

// ---------------------------- PTX helpers ----------------------------------
__device__ __forceinline__ uint32_t smem_u32(const void* p) {
    uint32_t a;
    asm("{ .reg .u64 t; cvta.to.shared.u64 t, %1; cvt.u32.u64 %0, t; }"
        : "=r"(a) : "l"(p));
    return a;
}
__device__ __forceinline__ uint32_t swz128(uint32_t off) {
    return off ^ ((off >> 3) & 0x70);
}
__device__ __forceinline__ void cpa16(uint32_t s, const void* g) {
    asm volatile("cp.async.cg.shared.global [%0], [%1], 16;" :: "r"(s), "l"(g));
}
#define CPA_COMMIT()  asm volatile("cp.async.commit_group;" ::: "memory")
#define CPA_WAIT1()   asm volatile("cp.async.wait_group 1;" ::: "memory")
#define CPA_WAIT0()   asm volatile("cp.async.wait_group 0;" ::: "memory")

__device__ __forceinline__ void ldsm4(uint32_t* r, uint32_t addr) {
    asm volatile("ldmatrix.sync.aligned.m8n8.x4.shared.b16 {%0,%1,%2,%3}, [%4];"
        : "=r"(r[0]), "=r"(r[1]), "=r"(r[2]), "=r"(r[3]) : "r"(addr));
}
__device__ __forceinline__ void mma_f16(float* c, const uint32_t* a,
                                        uint32_t b0, uint32_t b1) {
    asm volatile(
        "mma.sync.aligned.m16n8k16.row.col.f32.f16.f16.f32 "
        "{%0,%1,%2,%3}, {%4,%5,%6,%7}, {%8,%9}, {%0,%1,%2,%3};"
        : "+f"(c[0]), "+f"(c[1]), "+f"(c[2]), "+f"(c[3])
        : "r"(a[0]), "r"(a[1]), "r"(a[2]), "r"(a[3]), "r"(b0), "r"(b1));
}

// ---------------------------------------------------------------------------
// fp32 -> fp16 converts
// ---------------------------------------------------------------------------
__global__ __launch_bounds__(256) void convX_kernel(const float* __restrict__ src) {
    int i = blockIdx.x * 256 + threadIdx.x;          // float4 index
    float4 v = reinterpret_cast<const float4*>(src)[i];
    __half h[4] = {__float2half(v.x), __float2half(v.y),
                   __float2half(v.z), __float2half(v.w)};
    reinterpret_cast<uint2*>(g_Xh)[i] = *reinterpret_cast<uint2*>(h);
}

__global__ __launch_bounds__(256) void convW_kernel(
    const float* __restrict__ w0, const float* __restrict__ w1,
    const float* __restrict__ w2, const float* __restrict__ w3) {
    const float* src = (blockIdx.y == 0) ? w0 : (blockIdx.y == 1) ? w1
                     : (blockIdx.y == 2) ? w2 : w3;
    int i = blockIdx.x * 256 + threadIdx.x;          // float4 index
    float4 v = reinterpret_cast<const float4*>(src)[i];
    __half h[4] = {__float2half(v.x), __float2half(v.y),
                   __float2half(v.z), __float2half(v.w)};
    reinterpret_cast<uint2*>(g_Wh[blockIdx.y])[i] = *reinterpret_cast<uint2*>(h);
}

// ---------------------------------------------------------------------------
// fp16 HMMA GEMM: C[m,n] = sum_k A[m,k]*B[n,k], 1 MMA per product.
// Tile 128x128, K chunk 64, 8 warps (warp tile 32x64), 2 CTAs/SM.
// proj=1: A=X, blockIdx.y = 0/1/2 -> Wi(silu)->g_bin, Wf(sigm)->g_gate,
//         Wg(raw)->g_g.   proj=0: A=g_o, Wo (raw) -> Cext.
// ---------------------------------------------------------------------------
__global__ __launch_bounds__(256, 2) void gemm_f16(int proj, float* Cext) {
    extern __shared__ char smem[];
    const uint32_t sb = smem_u32(smem);
    const int tid  = threadIdx.x;
    const int lane = tid & 31;
    const int wid  = tid >> 5;
    const int wm   = wid & 3;      // 4 warps over M (32 rows each)
    const int wn   = wid >> 2;     // 2 warps over N (64 cols each)
    const int bn = blockIdx.x;
    const int bm = blockIdx.z;

    const __half *Aw, *Bw;
    float* C;
    int mode;                                    // 0 silu, 1 sigmoid, 2 raw
    if (proj) {
        Aw = g_Xh;
        int y = blockIdx.y;
        if (y == 0)      { Bw = g_Wh[0]; C = g_bin;  mode = 0; }
        else if (y == 1) { Bw = g_Wh[1]; C = g_gate; mode = 1; }
        else             { Bw = g_Wh[2]; C = g_g;    mode = 2; }
    } else { Aw = g_o; Bw = g_Wh[3]; C = Cext; mode = 2; }

    const size_t rowA = (size_t)bm * 128;
    const size_t rowB = (size_t)bn * 128;

    float acc[2][8][4];
    #pragma unroll
    for (int ma = 0; ma < 2; ma++)
        #pragma unroll
        for (int g = 0; g < 8; g++)
            #pragma unroll
            for (int q = 0; q < 4; q++) acc[ma][g][q] = 0.0f;

    // strength-reduced prefetch: one base pointer + base smem offset per
    // sub-buffer; per-thread loads are 32 rows apart (+4096B smem, swz128-
    // invariant). Pointers advance by KC per chunk.
    const int prow = tid >> 3;            // 0..31
    const int pch  = tid & 7;             // 16B chunk in 128B row
    const uint32_t so0 = swz128((uint32_t)prow * 128 + pch * 16);
    const __half* pA = Aw + (rowA + prow) * D_ + pch * 8;
    const __half* pB = Bw + (rowB + prow) * D_ + pch * 8;

    auto prefetch = [&](int c) {
        const uint32_t st = sb + (uint32_t)(c & 1) * STAGE;
        #pragma unroll
        for (int r = 0; r < 4; r++) {
            uint32_t so = so0 + r * 4096;
            size_t   go = (size_t)r * 32 * D_;
            cpa16(st + so,       pA + go);
            cpa16(st + SUB + so, pB + go);
        }
        pA += KC; pB += KC;
        CPA_COMMIT();
    };

    prefetch(0);
    prefetch(1);

    // ldsm bases, pre-swizzled. base bits 5,6 are zero pre-swizzle, so
    // swz128(base + ks*32) == swz128(base) ^ (ks*32).
    const int rowL = lane & 15;
    const int colL = lane >> 4;
    uint32_t arbS[2], brbS[4];
    #pragma unroll
    for (int ma = 0; ma < 2; ma++)
        arbS[ma] = swz128((uint32_t)(wm * 32 + ma * 16 + rowL) * 128 + colL * 16);
    #pragma unroll
    for (int g16 = 0; g16 < 4; g16++)
        brbS[g16] = swz128((uint32_t)(wn * 64 + g16 * 16 + rowL) * 128 + colL * 16)
                  + SUB;

    for (int c = 0; c < NKCH; c++) {
        if (c < NKCH - 1) { CPA_WAIT1(); } else { CPA_WAIT0(); }
        __syncthreads();

        const uint32_t st = sb + (uint32_t)(c & 1) * STAGE;
        #pragma unroll
        for (int ks = 0; ks < 4; ks++) {
            const uint32_t kx = (uint32_t)ks * 32;
            uint32_t ah[2][4];
            #pragma unroll
            for (int ma = 0; ma < 2; ma++)
                ldsm4(ah[ma], st + (arbS[ma] ^ kx));
            #pragma unroll
            for (int g16 = 0; g16 < 4; g16++) {
                uint32_t bh[4];
                ldsm4(bh, st + (brbS[g16] ^ kx));
                #pragma unroll
                for (int na = 0; na < 2; na++)
                    #pragma unroll
                    for (int ma = 0; ma < 2; ma++)
                        mma_f16(acc[ma][g16 * 2 + na], ah[ma], bh[na], bh[na + 2]);
            }
        }
        __syncthreads();
        if (c + 2 < NKCH) prefetch(c + 2);
    }

    // epilogue: direct float2 stores with fused activation
    #pragma unroll
    for (int ma = 0; ma < 2; ma++) {
        #pragma unroll
        for (int g = 0; g < 8; g++) {
            int n = (int)rowB + wn * 64 + (g >> 1) * 16 + (g & 1) * 8 + (lane & 3) * 2;
            size_t m0 = rowA + wm * 32 + ma * 16 + (lane >> 2);
            #pragma unroll
            for (int h = 0; h < 2; h++) {           // h=0: rows, h=1: rows+8
                float v0 = acc[ma][g][h * 2 + 0];
                float v1 = acc[ma][g][h * 2 + 1];
                if (mode == 0)      { v0 = v0 * fsigmoid(v0); v1 = v1 * fsigmoid(v1); }
                else if (mode == 1) { v0 = fsigmoid(v0);      v1 = fsigmoid(v1); }
                float2 pr = make_float2(v0, v1);
                *reinterpret_cast<float2*>(&C[(m0 + h * 8) * D_ + n]) = pr;
            }
        }
    }
}

// ---------------------------------------------------------------------------
// Chunked linear-recurrence scan: h_t = a_t*h_{t-1} + b_t,  b_t = si*(1-a_t)
// ---------------------------------------------------------------------------
__global__ void scan_pass1_kernel() {
    int d = blockIdx.x * 256 + threadIdx.x;
    int c = blockIdx.y;
    int b = blockIdx.z;
    size_t base = ((size_t)b * L_ + (size_t)c * LCHUNK) * D_ + d;
    float a = 1.0f, h = 0.0f;
    #pragma unroll 4
    for (int t = 0; t < LCHUNK; t++) {
        float gt = g_gate[base + (size_t)t * D_];
        float si = g_bin [base + (size_t)t * D_];
        h = fmaf(gt, h, si * (1.0f - gt));
        a *= gt;
    }
    size_t idx = ((size_t)b * NCHUNK + c) * D_ + d;
    g_cA[idx] = a;
    g_cH[idx] = h;
}

__global__ void scan_pass2_kernel() {
    int d = blockIdx.x * 256 + threadIdx.x;
    int b = blockIdx.y;
    float h = 0.0f;
    #pragma unroll
    for (int c = 0; c < NCHUNK; c++) {
        size_t idx = ((size_t)b * NCHUNK + c) * D_ + d;
        g_pre[idx] = h;
        h = fmaf(g_cA[idx], h, g_cH[idx]);
    }
}

__global__ void scan_pass3_kernel() {
    int d = blockIdx.x * 256 + threadIdx.x;
    int c = blockIdx.y;
    int b = blockIdx.z;
    size_t base = ((size_t)b * L_ + (size_t)c * LCHUNK) * D_ + d;
    float h = g_pre[((size_t)b * NCHUNK + c) * D_ + d];
    #pragma unroll 4
    for (int t = 0; t < LCHUNK; t++) {
        size_t p = base + (size_t)t * D_;
        float gt = g_gate[p];
        float si = g_bin [p];
        h = fmaf(gt, h, si * (1.0f - gt));
        g_bin[p] = h;           // o overwrites silu(i) in place
    }
}

// ---------------------------------------------------------------------------
// RMSNorm(g)*weight*swish(o); writes fp16 for the output GEMM.
// ---------------------------------------------------------------------------
__global__ __launch_bounds__(256) void rms_gate_kernel(const float* __restrict__ gw) {
    const int m = blockIdx.x;
    const int tid = threadIdx.x;
    const float4* grow = reinterpret_cast<const float4*>(g_g  + (size_t)m * D_);
    const float4* orow = reinterpret_cast<const float4*>(g_bin + (size_t)m * D_);
    const float4* wrow = reinterpret_cast<const float4*>(gw);

    float4 gv[2];
    float ss = 0.0f;
    #pragma unroll
    for (int s = 0; s < 2; s++) {
        gv[s] = grow[tid + s * 256];
        ss += gv[s].x * gv[s].x + gv[s].y * gv[s].y
            + gv[s].z * gv[s].z + gv[s].w * gv[s].w;
    }

    __shared__ float sh[8];
    __shared__ float tot;
    int lane = tid & 31, wid = tid >> 5;
    #pragma unroll
    for (int o = 16; o > 0; o >>= 1) ss += __shfl_xor_sync(0xffffffffu, ss, o);
    if (lane == 0) sh[wid] = ss;
    __syncthreads();
    if (wid == 0) {
        float v = (lane < 8) ? sh[lane] : 0.0f;
        #pragma unroll
        for (int o = 4; o > 0; o >>= 1) v += __shfl_xor_sync(0xffffffffu, v, o);
        if (lane == 0) tot = v;
    }
    __syncthreads();

    float rms = rsqrtf(tot * (1.0f / D_) + 1e-5f);

    #pragma unroll
    for (int s = 0; s < 2; s++) {
        float4 o4 = orow[tid + s * 256];
        float4 w4 = wrow[tid + s * 256];
        __half h[4];
        h[0] = __float2half(gv[s].x * rms * w4.x * (o4.x * fsigmoid(o4.x)));
        h[1] = __float2half(gv[s].y * rms * w4.y * (o4.y * fsigmoid(o4.y)));
        h[2] = __float2half(gv[s].z * rms * w4.z * (o4.z * fsigmoid(o4.z)));
        h[3] = __float2half(gv[s].w * rms * w4.w * (o4.w * fsigmoid(o4.w)));
        size_t b4 = (size_t)m * (D_ / 4) + tid + s * 256;
        reinterpret_cast<uint2*>(g_o)[b4] = *reinterpret_cast<uint2*>(h);
    }
}

// ---------------------------------------------------------------------------
extern "C" void kernel_launch(void* const* d_in, const int* in_sizes, int n_in,
                              void* d_out, int out_size)
{
    const float* X  = (const float*)d_in[0];
    const float* Wi = (const float*)d_in[1];
    const float* Wf = (const float*)d_in[2];
    const float* Wg = (const float*)d_in[3];
    const float* gw = (const float*)d_in[4];
    const float* Wo = (const float*)d_in[5];
    float* Y = (float*)d_out;

    static int smem_set = 0;
    if (!smem_set) {
        cudaFuncSetAttribute(gemm_f16,
            cudaFuncAttributeMaxDynamicSharedMemorySize, SMEM_TOTAL);
        smem_set = 1;
    }

    // fp32 -> fp16 converts
    convX_kernel<<<(M_ * D_ / 4) / 256, 256>>>(X);
    convW_kernel<<<dim3((D_ * D_ / 4) / 256, 4), 256>>>(Wi, Wf, Wg, Wo);

    // fused i/f/g projections (1-MMA each): grid y = weight
    gemm_f16<<<dim3(D_ / 128, 3, M_ / 128), 256, SMEM_TOTAL>>>(1, Y);

    scan_pass1_kernel<<<dim3(D_ / 256, NCHUNK, B_), 256>>>();
    scan_pass2_kernel<<<dim3(D_ / 256, B_), 256>>>();
    scan_pass3_kernel<<<dim3(D_ / 256, NCHUNK, B_), 256>>>();

    rms_gate_kernel<<<M_, 256>>>(gw);

    // out @ Wo^T -> Y (1-MMA)
    gemm_f16<<<dim3(D_ / 128, 1, M_ / 128), 256, SMEM_TOTAL>>>(0, Y);
}

// round 11
// speedup vs baseline: 3.1231x; 1.0277x over previous
#include <cuda_runtime.h>
#include <cuda_fp16.h>
#include <math.h>
#include <stdint.h>

#define B_ 4
#define L_ 4096
#define D_ 2048
#define M_ (B_*L_)            // 16384 rows
#define LCHUNK 128
#define NCHUNK (L_/LCHUNK)    // 32

// GEMM tiling: 128x128 tile, K chunk 64 fp16 (=128B row, SW128 swizzle)
#define KC 64
#define NKCH (D_/KC)          // 32
#define SUB 16384             // 128 rows * 128B
#define STAGE (2*SUB)         // A, B = 32KB
#define SMEM_TOTAL (2*STAGE)  // 64KB double buffered -> 2 CTAs/SM

// ---------------- scratch (device globals; no allocation allowed) ----------
__device__ __half g_gate[33554432];  // [M_, D_] sigmoid(f), fp16
__device__ __half g_bin [33554432];  // [M_, D_] silu(i); becomes swish(o) fp16
__device__ __half g_g   [33554432];  // [M_, D_] g projection, fp16
__device__ float g_cA  [B_*NCHUNK*D_];
__device__ float g_cH  [B_*NCHUNK*D_];
__device__ float g_pre [B_*NCHUNK*D_];
__device__ __half g_Xh[33554432];        // X (fp16 rounded)
__device__ __half g_Wh[4][4194304];      // Wi,Wf,Wg,Wo (fp16 rounded)
__device__ __half g_o[33554432];         // rms-gated out (fp16)

__device__ __forceinline__ float fsigmoid(float x) {
    return 1.0f / (1.0f + __expf(-x));
}

// ---------------------------- PTX helpers ----------------------------------
__device__ __forceinline__ uint32_t smem_u32(const void* p) {
    uint32_t a;
    asm("{ .reg .u64 t; cvta.to.shared.u64 t, %1; cvt.u32.u64 %0, t; }"
        : "=r"(a) : "l"(p));
    return a;
}
__device__ __forceinline__ uint32_t swz128(uint32_t off) {
    return off ^ ((off >> 3) & 0x70);
}
__device__ __forceinline__ void cpa16(uint32_t s, const void* g) {
    asm volatile("cp.async.cg.shared.global [%0], [%1], 16;" :: "r"(s), "l"(g));
}
#define CPA_COMMIT()  asm volatile("cp.async.commit_group;" ::: "memory")
#define CPA_WAIT1()   asm volatile("cp.async.wait_group 1;" ::: "memory")
#define CPA_WAIT0()   asm volatile("cp.async.wait_group 0;" ::: "memory")

__device__ __forceinline__ void ldsm4(uint32_t* r, uint32_t addr) {
    asm volatile("ldmatrix.sync.aligned.m8n8.x4.shared.b16 {%0,%1,%2,%3}, [%4];"
        : "=r"(r[0]), "=r"(r[1]), "=r"(r[2]), "=r"(r[3]) : "r"(addr));
}
__device__ __forceinline__ void mma_f16(float* c, const uint32_t* a,
                                        uint32_t b0, uint32_t b1) {
    asm volatile(
        "mma.sync.aligned.m16n8k16.row.col.f32.f16.f16.f32 "
        "{%0,%1,%2,%3}, {%4,%5,%6,%7}, {%8,%9}, {%0,%1,%2,%3};"
        : "+f"(c[0]), "+f"(c[1]), "+f"(c[2]), "+f"(c[3])
        : "r"(a[0]), "r"(a[1]), "r"(a[2]), "r"(a[3]), "r"(b0), "r"(b1));
}

// ---------------------------------------------------------------------------
// fp32 -> fp16 converts
// ---------------------------------------------------------------------------
__global__ __launch_bounds__(256) void convX_kernel(const float* __restrict__ src) {
    int i = blockIdx.x * 256 + threadIdx.x;          // float4 index
    float4 v = reinterpret_cast<const float4*>(src)[i];
    __half h[4] = {__float2half(v.x), __float2half(v.y),
                   __float2half(v.z), __float2half(v.w)};
    reinterpret_cast<uint2*>(g_Xh)[i] = *reinterpret_cast<uint2*>(h);
}

__global__ __launch_bounds__(256) void convW_kernel(
    const float* __restrict__ w0, const float* __restrict__ w1,
    const float* __restrict__ w2, const float* __restrict__ w3) {
    const float* src = (blockIdx.y == 0) ? w0 : (blockIdx.y == 1) ? w1
                     : (blockIdx.y == 2) ? w2 : w3;
    int i = blockIdx.x * 256 + threadIdx.x;          // float4 index
    float4 v = reinterpret_cast<const float4*>(src)[i];
    __half h[4] = {__float2half(v.x), __float2half(v.y),
                   __float2half(v.z), __float2half(v.w)};
    reinterpret_cast<uint2*>(g_Wh[blockIdx.y])[i] = *reinterpret_cast<uint2*>(h);
}

// ---------------------------------------------------------------------------
// fp16 HMMA GEMM: C[m,n] = sum_k A[m,k]*B[n,k], 1 MMA per product.
// Tile 128x128, K chunk 64, 8 warps (warp tile 32x64), 2 CTAs/SM.
// proj=1: A=X, blockIdx.y = 0/1/2 -> Wi(silu)->g_bin, Wf(sigm)->g_gate,
//         Wg(raw)->g_g (all fp16).   proj=0: A=g_o, Wo -> Cext (fp32).
// ---------------------------------------------------------------------------
__global__ __launch_bounds__(256, 2) void gemm_f16(int proj, float* Cext) {
    extern __shared__ char smem[];
    const uint32_t sb = smem_u32(smem);
    const int tid  = threadIdx.x;
    const int lane = tid & 31;
    const int wid  = tid >> 5;
    const int wm   = wid & 3;      // 4 warps over M (32 rows each)
    const int wn   = wid >> 2;     // 2 warps over N (64 cols each)
    const int bn = blockIdx.x;
    const int bm = blockIdx.z;

    const __half *Aw, *Bw;
    __half* Ch = nullptr;
    int mode;                                    // 0 silu, 1 sigmoid, 2 raw
    if (proj) {
        Aw = g_Xh;
        int y = blockIdx.y;
        if (y == 0)      { Bw = g_Wh[0]; Ch = g_bin;  mode = 0; }
        else if (y == 1) { Bw = g_Wh[1]; Ch = g_gate; mode = 1; }
        else             { Bw = g_Wh[2]; Ch = g_g;    mode = 2; }
    } else { Aw = g_o; Bw = g_Wh[3]; mode = 3; }

    const size_t rowA = (size_t)bm * 128;
    const size_t rowB = (size_t)bn * 128;

    float acc[2][8][4];
    #pragma unroll
    for (int ma = 0; ma < 2; ma++)
        #pragma unroll
        for (int g = 0; g < 8; g++)
            #pragma unroll
            for (int q = 0; q < 4; q++) acc[ma][g][q] = 0.0f;

    // strength-reduced prefetch: one base pointer + base smem offset per
    // sub-buffer; per-thread loads are 32 rows apart (+4096B smem, swz128-
    // invariant). Pointers advance by KC per chunk.
    const int prow = tid >> 3;            // 0..31
    const int pch  = tid & 7;             // 16B chunk in 128B row
    const uint32_t so0 = swz128((uint32_t)prow * 128 + pch * 16);
    const __half* pA = Aw + (rowA + prow) * D_ + pch * 8;
    const __half* pB = Bw + (rowB + prow) * D_ + pch * 8;

    auto prefetch = [&](int c) {
        const uint32_t st = sb + (uint32_t)(c & 1) * STAGE;
        #pragma unroll
        for (int r = 0; r < 4; r++) {
            uint32_t so = so0 + r * 4096;
            size_t   go = (size_t)r * 32 * D_;
            cpa16(st + so,       pA + go);
            cpa16(st + SUB + so, pB + go);
        }
        pA += KC; pB += KC;
        CPA_COMMIT();
    };

    prefetch(0);
    prefetch(1);

    // ldsm bases, pre-swizzled. base bits 5,6 are zero pre-swizzle, so
    // swz128(base + ks*32) == swz128(base) ^ (ks*32).
    const int rowL = lane & 15;
    const int colL = lane >> 4;
    uint32_t arbS[2], brbS[4];
    #pragma unroll
    for (int ma = 0; ma < 2; ma++)
        arbS[ma] = swz128((uint32_t)(wm * 32 + ma * 16 + rowL) * 128 + colL * 16);
    #pragma unroll
    for (int g16 = 0; g16 < 4; g16++)
        brbS[g16] = swz128((uint32_t)(wn * 64 + g16 * 16 + rowL) * 128 + colL * 16)
                  + SUB;

    for (int c = 0; c < NKCH; c++) {
        if (c < NKCH - 1) { CPA_WAIT1(); } else { CPA_WAIT0(); }
        __syncthreads();

        const uint32_t st = sb + (uint32_t)(c & 1) * STAGE;
        #pragma unroll
        for (int ks = 0; ks < 4; ks++) {
            const uint32_t kx = (uint32_t)ks * 32;
            uint32_t ah[2][4];
            #pragma unroll
            for (int ma = 0; ma < 2; ma++)
                ldsm4(ah[ma], st + (arbS[ma] ^ kx));
            #pragma unroll
            for (int g16 = 0; g16 < 4; g16++) {
                uint32_t bh[4];
                ldsm4(bh, st + (brbS[g16] ^ kx));
                #pragma unroll
                for (int na = 0; na < 2; na++)
                    #pragma unroll
                    for (int ma = 0; ma < 2; ma++)
                        mma_f16(acc[ma][g16 * 2 + na], ah[ma], bh[na], bh[na + 2]);
            }
        }
        __syncthreads();
        if (c + 2 < NKCH) prefetch(c + 2);
    }

    // epilogue: fused activation; proj -> half2 stores, out -> float2 stores
    #pragma unroll
    for (int ma = 0; ma < 2; ma++) {
        #pragma unroll
        for (int g = 0; g < 8; g++) {
            int n = (int)rowB + wn * 64 + (g >> 1) * 16 + (g & 1) * 8 + (lane & 3) * 2;
            size_t m0 = rowA + wm * 32 + ma * 16 + (lane >> 2);
            #pragma unroll
            for (int h = 0; h < 2; h++) {           // h=0: rows, h=1: rows+8
                float v0 = acc[ma][g][h * 2 + 0];
                float v1 = acc[ma][g][h * 2 + 1];
                if (mode == 0)      { v0 = v0 * fsigmoid(v0); v1 = v1 * fsigmoid(v1); }
                else if (mode == 1) { v0 = fsigmoid(v0);      v1 = fsigmoid(v1); }
                size_t off = (m0 + h * 8) * D_ + n;
                if (mode == 3) {
                    *reinterpret_cast<float2*>(&Cext[off]) = make_float2(v0, v1);
                } else {
                    *reinterpret_cast<__half2*>(&Ch[off]) =
                        __floats2half2_rn(v0, v1);
                }
            }
        }
    }
}

// ---------------------------------------------------------------------------
// Chunked linear-recurrence scan: h_t = a_t*h_{t-1} + b_t,  b_t = si*(1-a_t)
// fp16 storage, fp32 math; 2 channels (half2) per thread.
// ---------------------------------------------------------------------------
__global__ void scan_pass1_kernel() {
    int d2 = blockIdx.x * 256 + threadIdx.x;      // half2 column, 0..1023
    int c = blockIdx.y;
    int b = blockIdx.z;
    size_t base = ((size_t)b * L_ + (size_t)c * LCHUNK) * (D_ / 2) + d2;
    const __half2* gp = reinterpret_cast<const __half2*>(g_gate);
    const __half2* sp = reinterpret_cast<const __half2*>(g_bin);
    float2 a = make_float2(1.0f, 1.0f), h = make_float2(0.0f, 0.0f);
    #pragma unroll 4
    for (int t = 0; t < LCHUNK; t++) {
        float2 gt = __half22float2(gp[base + (size_t)t * (D_ / 2)]);
        float2 si = __half22float2(sp[base + (size_t)t * (D_ / 2)]);
        h.x = fmaf(gt.x, h.x, si.x * (1.0f - gt.x));
        h.y = fmaf(gt.y, h.y, si.y * (1.0f - gt.y));
        a.x *= gt.x; a.y *= gt.y;
    }
    size_t idx = ((size_t)b * NCHUNK + c) * (D_ / 2) + d2;
    reinterpret_cast<float2*>(g_cA)[idx] = a;
    reinterpret_cast<float2*>(g_cH)[idx] = h;
}

__global__ void scan_pass2_kernel() {
    int d2 = blockIdx.x * 256 + threadIdx.x;
    int b = blockIdx.y;
    float2 h = make_float2(0.0f, 0.0f);
    #pragma unroll
    for (int c = 0; c < NCHUNK; c++) {
        size_t idx = ((size_t)b * NCHUNK + c) * (D_ / 2) + d2;
        reinterpret_cast<float2*>(g_pre)[idx] = h;
        float2 a = reinterpret_cast<const float2*>(g_cA)[idx];
        float2 ch = reinterpret_cast<const float2*>(g_cH)[idx];
        h.x = fmaf(a.x, h.x, ch.x);
        h.y = fmaf(a.y, h.y, ch.y);
    }
}

// pass3: replay chunk from prefix, write swish(o) as fp16 (overwrites g_bin)
__global__ void scan_pass3_kernel() {
    int d2 = blockIdx.x * 256 + threadIdx.x;
    int c = blockIdx.y;
    int b = blockIdx.z;
    size_t base = ((size_t)b * L_ + (size_t)c * LCHUNK) * (D_ / 2) + d2;
    const __half2* gp = reinterpret_cast<const __half2*>(g_gate);
    __half2* sp = reinterpret_cast<__half2*>(g_bin);
    float2 h = reinterpret_cast<const float2*>(g_pre)[
        ((size_t)b * NCHUNK + c) * (D_ / 2) + d2];
    #pragma unroll 4
    for (int t = 0; t < LCHUNK; t++) {
        size_t p = base + (size_t)t * (D_ / 2);
        float2 gt = __half22float2(gp[p]);
        float2 si = __half22float2(sp[p]);
        h.x = fmaf(gt.x, h.x, si.x * (1.0f - gt.x));
        h.y = fmaf(gt.y, h.y, si.y * (1.0f - gt.y));
        float sw0 = h.x * fsigmoid(h.x);
        float sw1 = h.y * fsigmoid(h.y);
        sp[p] = __floats2half2_rn(sw0, sw1);     // swish(o) in place
    }
}

// ---------------------------------------------------------------------------
// RMSNorm(g)*weight*swish(o); writes fp16 for the output GEMM.
// g and swish(o) are fp16; math fp32.
// ---------------------------------------------------------------------------
__global__ __launch_bounds__(256) void rms_gate_kernel(const float* __restrict__ gw) {
    const int m = blockIdx.x;
    const int tid = threadIdx.x;
    const uint2* grow = reinterpret_cast<const uint2*>(g_g  + (size_t)m * D_);
    const uint2* srow = reinterpret_cast<const uint2*>(g_bin + (size_t)m * D_);
    const float4* wrow = reinterpret_cast<const float4*>(gw);

    float gv[2][4];
    float ss = 0.0f;
    #pragma unroll
    for (int s = 0; s < 2; s++) {
        uint2 packed = grow[tid + s * 256];
        float2 p0 = __half22float2(*reinterpret_cast<__half2*>(&packed.x));
        float2 p1 = __half22float2(*reinterpret_cast<__half2*>(&packed.y));
        gv[s][0] = p0.x; gv[s][1] = p0.y; gv[s][2] = p1.x; gv[s][3] = p1.y;
        ss += p0.x * p0.x + p0.y * p0.y + p1.x * p1.x + p1.y * p1.y;
    }

    __shared__ float sh[8];
    __shared__ float tot;
    int lane = tid & 31, wid = tid >> 5;
    #pragma unroll
    for (int o = 16; o > 0; o >>= 1) ss += __shfl_xor_sync(0xffffffffu, ss, o);
    if (lane == 0) sh[wid] = ss;
    __syncthreads();
    if (wid == 0) {
        float v = (lane < 8) ? sh[lane] : 0.0f;
        #pragma unroll
        for (int o = 4; o > 0; o >>= 1) v += __shfl_xor_sync(0xffffffffu, v, o);
        if (lane == 0) tot = v;
    }
    __syncthreads();

    float rms = rsqrtf(tot * (1.0f / D_) + 1e-5f);

    #pragma unroll
    for (int s = 0; s < 2; s++) {
        uint2 spk = srow[tid + s * 256];
        float2 s0 = __half22float2(*reinterpret_cast<__half2*>(&spk.x));
        float2 s1 = __half22float2(*reinterpret_cast<__half2*>(&spk.y));
        float sw[4] = {s0.x, s0.y, s1.x, s1.y};
        float4 w4 = wrow[tid + s * 256];
        float wv[4] = {w4.x, w4.y, w4.z, w4.w};
        __half h[4];
        #pragma unroll
        for (int q = 0; q < 4; q++)
            h[q] = __float2half(gv[s][q] * rms * wv[q] * sw[q]);
        size_t b4 = (size_t)m * (D_ / 4) + tid + s * 256;
        reinterpret_cast<uint2*>(g_o)[b4] = *reinterpret_cast<uint2*>(h);
    }
}

// ---------------------------------------------------------------------------
extern "C" void kernel_launch(void* const* d_in, const int* in_sizes, int n_in,
                              void* d_out, int out_size)
{
    const float* X  = (const float*)d_in[0];
    const float* Wi = (const float*)d_in[1];
    const float* Wf = (const float*)d_in[2];
    const float* Wg = (const float*)d_in[3];
    const float* gw = (const float*)d_in[4];
    const float* Wo = (const float*)d_in[5];
    float* Y = (float*)d_out;

    static int smem_set = 0;
    if (!smem_set) {
        cudaFuncSetAttribute(gemm_f16,
            cudaFuncAttributeMaxDynamicSharedMemorySize, SMEM_TOTAL);
        smem_set = 1;
    }

    // fp32 -> fp16 converts
    convX_kernel<<<(M_ * D_ / 4) / 256, 256>>>(X);
    convW_kernel<<<dim3((D_ * D_ / 4) / 256, 4), 256>>>(Wi, Wf, Wg, Wo);

    // fused i/f/g projections (1-MMA each): grid y = weight
    gemm_f16<<<dim3(D_ / 128, 3, M_ / 128), 256, SMEM_TOTAL>>>(1, Y);

    scan_pass1_kernel<<<dim3(D_ / 512, NCHUNK, B_), 256>>>();
    scan_pass2_kernel<<<dim3(D_ / 512, B_), 256>>>();
    scan_pass3_kernel<<<dim3(D_ / 512, NCHUNK, B_), 256>>>();

    rms_gate_kernel<<<M_, 256>>>(gw);

    // out @ Wo^T -> Y (1-MMA)
    gemm_f16<<<dim3(D_ / 128, 1, M_ / 128), 256, SMEM_TOTAL>>>(0, Y);
}